// round 9
// baseline (speedup 1.0000x reference)
#include <cuda_runtime.h>
#include <cuda_fp16.h>
#include <math.h>
#include <stdint.h>

#define KNB 40
#define DF 128
#define MDIM 384
#define HH 4
#define DHD 96
#define BB 128
#define R1 409600
#define R2 10240
#define KX 512
#define NOUT 768
#define NPB 8
#define KV2 776              // padded halves per KV row in smem
#define KVBUFH (KNB * KV2)   // 31040 halves

// ---------------- scratch (__device__ globals, no allocation) ----------------
__device__ __align__(16) __half g_X[(size_t)R1 * KX];          // gathered features (fp16)
__device__ __align__(16) __half g_Wt[2 * NOUT * KX];           // fused K|V weights [l][n][k]
__device__ __align__(16) __half g_KV[(size_t)R1 * NOUT];       // K|V projections (fp16)
__device__ float g_qconst[2][384];
__device__ float g_WoM1[2][384 * 128];
__device__ float g_h1[R2 * DF];
__device__ float g_h2[256 * DF];

// ---------------- helpers ----------------
__device__ __forceinline__ uint32_t smem_u32(const void* p) {
    return (uint32_t)__cvta_generic_to_shared((void*)p);
}
#define CP_ASYNC16(dst, src) \
    asm volatile("cp.async.cg.shared.global [%0], [%1], 16;" :: "r"(dst), "l"(src) : "memory")
#define CP_COMMIT() asm volatile("cp.async.commit_group;" ::: "memory")
#define CP_WAIT(n)  asm volatile("cp.async.wait_group %0;" :: "n"(n) : "memory")
#define LDSM_X4(d0, d1, d2, d3, addr) \
    asm volatile("ldmatrix.sync.aligned.m8n8.x4.shared.b16 {%0,%1,%2,%3}, [%4];" \
        : "=r"(d0), "=r"(d1), "=r"(d2), "=r"(d3) : "r"(addr))

__device__ __forceinline__ void mma16816(float* c, uint32_t a0, uint32_t a1,
                                         uint32_t a2, uint32_t a3,
                                         uint32_t b0, uint32_t b1) {
    asm volatile(
        "mma.sync.aligned.m16n8k16.row.col.f32.f16.f16.f32 "
        "{%0,%1,%2,%3}, {%4,%5,%6,%7}, {%8,%9}, {%0,%1,%2,%3};"
        : "+f"(c[0]), "+f"(c[1]), "+f"(c[2]), "+f"(c[3])
        : "r"(a0), "r"(a1), "r"(a2), "r"(a3), "r"(b0), "r"(b1));
}

// FMA-pipe cos: quadrant range reduction + polys on [-pi/4, pi/4].
// Accurate to ~1e-5 for |x| <= ~2000 rad; fp16 downstream dominates error.
__device__ __forceinline__ float fcospoly(float x) {
    float n = rintf(x * 0.6366197723675814f);          // x * 2/pi
    float r = fmaf(n, -1.5707963705062866e0f, x);      // hi of pi/2
    r = fmaf(n, 4.3711388286737929e-8f, r);            // lo correction
    int q = ((int)n) & 3;
    float r2 = r * r;
    float pc = fmaf(r2, fmaf(r2, fmaf(r2, -1.388888889e-3f, 4.166666667e-2f), -0.5f), 1.0f);
    float ps = r * fmaf(r2, fmaf(r2, fmaf(r2, -1.984126984e-4f, 8.333333333e-3f), -1.666666667e-1f), 1.0f);
    float v = (q & 1) ? ps : pc;
    return ((q + 1) & 2) ? -v : v;
}

// ------------- precompute: fused transposed K|V weights (fp16) ---------------
__global__ void pre_weights(const float* __restrict__ Wrel,
                            const float* __restrict__ Wk,
                            const float* __restrict__ Wv) {
    int l = blockIdx.x / NOUT;
    int n = blockIdx.x % NOUT;
    int t = threadIdx.x;   // 128
    const float* Ws = ((n < MDIM) ? Wk : Wv) + (size_t)l * MDIM * MDIM;
    int nc = (n < MDIM) ? n : n - MDIM;
    const float* wr0 = Wrel + ((size_t)(l * 2 + 0) * DF + t) * DF;
    const float* wr1 = Wrel + ((size_t)(l * 2 + 1) * DF + t) * DF;
    float v0 = 0.f, v1 = 0.f;
    for (int j = 0; j < DF; j++) {
        float w = Ws[(size_t)j * MDIM + nc];
        v0 = fmaf(wr0[j], w, v0);
        v1 = fmaf(wr1[j], w, v1);
    }
    size_t base = ((size_t)l * NOUT + n) * KX;
    g_Wt[base + t]        = __float2half_rn(v0);
    g_Wt[base + DF + t]   = __float2half_rn(v1);
    g_Wt[base + 256 + t]  = __float2half_rn(Ws[(size_t)(DF + t) * MDIM + nc]);
    g_Wt[base + 384 + t]  = __float2half_rn(Ws[(size_t)(256 + t) * MDIM + nc]);
}

// ---------------- precompute: qconst + Wo@Wm1 ----------------
__global__ void pre_misc(const float* __restrict__ Wq,
                         const float* __restrict__ Wo,
                         const float* __restrict__ Wm1,
                         const float* __restrict__ phase) {
    int bid = blockIdx.x;          // 770 = 2*(384+1)
    int l = bid / 385;
    int r = bid % 385;
    int tid = threadIdx.x;         // 384
    if (r == 384) {
        float acc = 0.f;
        for (int j = 0; j < 128; j++)
            acc = fmaf(cosf(phase[j]), Wq[(size_t)l * MDIM * MDIM + (256 + j) * MDIM + tid], acc);
        g_qconst[l][tid] = acc;
    } else if (tid < 128) {
        float acc = 0.f;
        for (int j = 0; j < MDIM; j++)
            acc = fmaf(Wo[(size_t)l * MDIM * MDIM + r * MDIM + j],
                       Wm1[(size_t)(l * 512 + j) * 128 + tid], acc);
        g_WoM1[l][r * 128 + tid] = acc;
    }
}

// ---------------- gather: build X rows (fp16), 4 rows per CTA ----------------
__global__ void gather_kernel(int layer, const int* __restrict__ nghNode,
                              const int* __restrict__ nghEidx,
                              const float* __restrict__ nghT,
                              const int* __restrict__ nghEt,
                              const float* __restrict__ parentT,
                              const float* __restrict__ n_feat,
                              const float* __restrict__ mem_tab,
                              const float* __restrict__ e_feat,
                              const float* __restrict__ freq,
                              const float* __restrict__ phase) {
    int r = blockIdx.x * 4 + (threadIdx.x >> 7);
    int j = threadIdx.x & 127;
    int node = nghNode[r];
    int eidx = nghEidx[r];
    int et = nghEt[r];
    int p = r / KNB;
    float tq = (layer == 0) ? parentT[p] : parentT[p & (BB - 1)];
    float dt = tq - nghT[r];
    float nf = (layer == 0)
        ? n_feat[(size_t)node * DF + j] + mem_tab[(size_t)node * DF + j]
        : g_h1[(size_t)r * DF + j];
    float ef = e_feat[(size_t)eidx * DF + j];
    float tf = fcospoly(fmaf(dt, freq[j], phase[j]));
    size_t base = (size_t)r * KX;
    g_X[base + j]        = __float2half_rn((et == 0) ? nf : 0.f);
    g_X[base + DF + j]   = __float2half_rn((et == 1) ? nf : 0.f);
    g_X[base + 256 + j]  = __float2half_rn(ef);
    g_X[base + 384 + j]  = __float2half_rn(tf);
}

// ---------------- HMMA GEMM: KV = X @ Wt' ----------------
// CTA tile 128x128, K=512 in 8 chunks of 64, 3-stage cp.async pipeline,
// one barrier per chunk. 8 warps (4M x 2N), warp tile 32x64.
// Grid: (N-blocks, M-blocks) -> N fastest so X tiles hit L2 across N sweep.
#define STR 72                         // padded smem stride in halves (144B rows)
#define ABYTES (128 * STR * 2)         // 18432
#define BUFB   (2 * ABYTES)            // 36864 per stage (A + B)
__global__ __launch_bounds__(256, 2)
void gemm_kernel(int layer) {
    extern __shared__ char smem[];
    const uint32_t smem_base = smem_u32(smem);
    const int tid = threadIdx.x;
    const int wid = tid >> 5;
    const int lane = tid & 31;
    const int n0 = blockIdx.x * 128;
    const int m0 = blockIdx.y * 128;
    const int wm = wid >> 1;           // 0..3
    const int wn = wid & 1;            // 0..1
    const int mbase = wm * 32;
    const int nbase = wn * 64;

    const int lrow = lane & 15;                      // A: row within 16
    const int akh  = (lane >> 4) * 8;                // A: k-half select
    const int brow = (lane & 7) + ((lane >> 4) * 8); // B: row within 16
    const int bkh  = ((lane >> 3) & 1) * 8;          // B: k-half select

    const __half* gW = g_Wt + (size_t)layer * NOUT * KX;

    float acc[2][8][4];
#pragma unroll
    for (int mt = 0; mt < 2; mt++)
#pragma unroll
        for (int nt = 0; nt < 8; nt++)
#pragma unroll
            for (int q = 0; q < 4; q++) acc[mt][nt][q] = 0.f;

    auto stage = [&](int c) {
        const int kb = c * 64;
        const uint32_t sbase = smem_base + (c % 3) * BUFB;
#pragma unroll
        for (int it = 0; it < 8; it++) {
            int i = tid + it * 256;                // 0..2047
            int isB = i >> 10;
            int j = i & 1023;
            int row = j >> 3, seg = j & 7;
            uint32_t dst = sbase + isB * ABYTES + (uint32_t)(row * STR + seg * 8) * 2;
            const __half* src = isB ? (gW + (size_t)(n0 + row) * KX + kb + seg * 8)
                                    : (g_X + (size_t)(m0 + row) * KX + kb + seg * 8);
            CP_ASYNC16(dst, src);
        }
        CP_COMMIT();
    };

    stage(0);
    stage(1);
    for (int c = 0; c < 8; c++) {
        if (c < 7) CP_WAIT(1); else CP_WAIT(0);
        __syncthreads();
        const uint32_t sA = smem_base + (c % 3) * BUFB;
        const uint32_t sB = sA + ABYTES;
#pragma unroll
        for (int ks = 0; ks < 4; ks++) {
            const int k16 = ks * 16;
            uint32_t bf[8][2];
#pragma unroll
            for (int nt2 = 0; nt2 < 4; nt2++) {
                uint32_t d0, d1, d2, d3;
                uint32_t addr = sB + (uint32_t)((nbase + nt2 * 16 + brow) * STR + k16 + bkh) * 2;
                LDSM_X4(d0, d1, d2, d3, addr);
                bf[nt2 * 2][0] = d0; bf[nt2 * 2][1] = d1;
                bf[nt2 * 2 + 1][0] = d2; bf[nt2 * 2 + 1][1] = d3;
            }
#pragma unroll
            for (int mt = 0; mt < 2; mt++) {
                uint32_t a0, a1, a2, a3;
                uint32_t addr = sA + (uint32_t)((mbase + mt * 16 + lrow) * STR + k16 + akh) * 2;
                LDSM_X4(a0, a1, a2, a3, addr);
#pragma unroll
                for (int nt = 0; nt < 8; nt++)
                    mma16816(acc[mt][nt], a0, a1, a2, a3, bf[nt][0], bf[nt][1]);
            }
        }
        // buffer (c+2)%3 is disjoint from c%3 (compute) and (c+1)%3 (in flight),
        // and this warp's reads of it finished before this chunk's barrier.
        if (c + 2 < 8) stage(c + 2);
    }

    // epilogue: write fp16 results
#pragma unroll
    for (int mt = 0; mt < 2; mt++) {
#pragma unroll
        for (int nt = 0; nt < 8; nt++) {
            int r = m0 + mbase + mt * 16 + (lane >> 2);
            int ccol = n0 + nbase + nt * 8 + (lane & 3) * 2;
            *(__half2*)(g_KV + (size_t)r * NOUT + ccol) =
                __floats2half2_rn(acc[mt][nt][0], acc[mt][nt][1]);
            *(__half2*)(g_KV + (size_t)(r + 8) * NOUT + ccol) =
                __floats2half2_rn(acc[mt][nt][2], acc[mt][nt][3]);
        }
    }
}

// ---------------- attention + MLP: 8 query nodes per CTA, 2 CTAs/SM ----------
// Single KV smem buffer (fp16, cp.async); warp-parallel softmax.
__global__ __launch_bounds__(256, 2)
void attn_kernel(int layer, const int* __restrict__ nghNode,
                 const int* __restrict__ srcA, const int* __restrict__ srcB,
                 const float* __restrict__ n_feat, const float* __restrict__ mem_tab,
                 const float* __restrict__ Wq, const float* __restrict__ Wm1,
                 const float* __restrict__ bm1, const float* __restrict__ Wm2,
                 const float* __restrict__ bm2) {
    extern __shared__ float sm[];
    __half* sKVh = (__half*)sm;              // 31040 halves = 15520 floats
    float* sSRC  = sm + 15520;               // 8*128
    float* sQ    = sm + 16544;               // 8*384
    float* sO    = sm + 19616;               // 8*384
    float* sS    = sm + 22688;               // 160
    float* sA1   = sm + 22848;               // 8*128
    int*   sMask = (int*)(sm + 23872);       // 40  (end 23912 floats = 95648 B)
    const int tid = threadIdx.x;
    const int nb = blockIdx.x;
    const uint32_t smem_base = smem_u32(sm);

    for (int i = tid; i < NPB * DF; i += 256) {
        int node = i >> 7, j = i & 127;
        int n = nb * NPB + node;
        int sid = (layer == 0) ? srcA[n] : ((n < BB) ? srcA[n] : srcB[n - BB]);
        sSRC[i] = n_feat[(size_t)sid * DF + j] + mem_tab[(size_t)sid * DF + j];
    }

    auto stageKV = [&](int i) {
        const __half* src = g_KV + (size_t)(nb * NPB + i) * KNB * NOUT;
        for (int v = tid; v < KNB * 96; v += 256) {
            int row = v / 96, c8 = v % 96;
            CP_ASYNC16(smem_base + (uint32_t)(row * KV2 + c8 * 8) * 2,
                       src + (size_t)row * NOUT + c8 * 8);
        }
        CP_COMMIT();
    };
    stageKV(0);
    __syncthreads();

    // Q projection for all 8 nodes (weights loaded once, reused x8)
    {
        float acc0[NPB], acc1[NPB];
#pragma unroll
        for (int i = 0; i < NPB; i++) { acc0[i] = 0.f; acc1[i] = 0.f; }
        const float* wq = Wq + (size_t)layer * MDIM * MDIM;
        for (int m = 0; m < DF; m++) {
            float w0 = wq[(size_t)m * MDIM + tid];
            float w1 = (tid < 128) ? wq[(size_t)m * MDIM + 256 + tid] : 0.f;
#pragma unroll
            for (int i = 0; i < NPB; i++) {
                float x = sSRC[i * DF + m];
                acc0[i] = fmaf(x, w0, acc0[i]);
                acc1[i] = fmaf(x, w1, acc1[i]);
            }
        }
#pragma unroll
        for (int i = 0; i < NPB; i++) {
            sQ[i * MDIM + tid] = acc0[i] + g_qconst[layer][tid];
            if (tid < 128) sQ[i * MDIM + 256 + tid] = acc1[i] + g_qconst[layer][256 + tid];
        }
    }

    for (int i = 0; i < NPB; i++) {
        const int n = nb * NPB + i;
        if (tid < KNB) sMask[tid] = (nghNode[n * KNB + tid] == 0) ? 1 : 0;
        CP_WAIT(0);
        __syncthreads();
        // scores
        if (tid < HH * KNB) {
            int h = tid / KNB, row = tid % KNB;
            const __half2* kr2 = (const __half2*)(sKVh + row * KV2 + h * DHD);
            const float* qk = sQ + i * MDIM + h * DHD;
            float s = 0.f;
#pragma unroll
            for (int d2 = 0; d2 < DHD / 2; d2++) {
                float2 kf = __half22float2(kr2[d2]);
                s = fmaf(qk[2 * d2], kf.x, s);
                s = fmaf(qk[2 * d2 + 1], kf.y, s);
            }
            s *= 0.10206207261596577f;   // 1/sqrt(96)
            if (sMask[row]) s = -1000000000.0f;
            sS[h * KNB + row] = s;
        }
        __syncthreads();
        // warp-parallel softmax: warp h handles head h
        if (tid < 128) {
            int h = tid >> 5, lane = tid & 31;
            float v0 = sS[h * KNB + lane];
            float v1 = (lane < 8) ? sS[h * KNB + 32 + lane] : -INFINITY;
            float mx = fmaxf(v0, v1);
#pragma unroll
            for (int o = 16; o > 0; o >>= 1)
                mx = fmaxf(mx, __shfl_xor_sync(0xFFFFFFFF, mx, o));
            float e0 = expf(v0 - mx);
            float e1 = (lane < 8) ? expf(v1 - mx) : 0.f;
            float sum = e0 + e1;
#pragma unroll
            for (int o = 16; o > 0; o >>= 1)
                sum += __shfl_xor_sync(0xFFFFFFFF, sum, o);
            float inv = 1.f / sum;
            sS[h * KNB + lane] = e0 * inv;
            if (lane < 8) sS[h * KNB + 32 + lane] = e1 * inv;
        }
        __syncthreads();
        // o = a @ V
        for (int cc = tid; cc < MDIM; cc += 256) {
            int h = cc / DHD;
            const float* a = sS + h * KNB;
            float o = 0.f;
            for (int k = 0; k < KNB; k++)
                o = fmaf(a[k], __half2float(sKVh[k * KV2 + MDIM + cc]), o);
            sO[i * MDIM + cc] = o;
        }
        __syncthreads();
        if (i < 7) stageKV(i + 1);    // single buffer: all reads of node i done
    }

    // MLP layer 1 (Wo folded into WoM1): 2 thread-halves x 4 nodes each
    {
        const int half = tid >> 7, col = tid & 127;
        float a[4];
#pragma unroll
        for (int i = 0; i < 4; i++) a[i] = bm1[layer * DF + col];
        const float* w1 = &g_WoM1[layer][col];
        for (int m = 0; m < MDIM; m++) {
            float w = w1[m * DF];
#pragma unroll
            for (int i = 0; i < 4; i++)
                a[i] = fmaf(sO[(half * 4 + i) * MDIM + m], w, a[i]);
        }
        const float* w1b = Wm1 + (size_t)(layer * 512 + MDIM) * DF + col;
        for (int m = 0; m < DF; m++) {
            float w = w1b[m * DF];
#pragma unroll
            for (int i = 0; i < 4; i++)
                a[i] = fmaf(sSRC[(half * 4 + i) * DF + m], w, a[i]);
        }
#pragma unroll
        for (int i = 0; i < 4; i++) sA1[(half * 4 + i) * DF + col] = fmaxf(a[i], 0.f);
    }
    __syncthreads();
    {
        const int half = tid >> 7, col = tid & 127;
        float a[4];
#pragma unroll
        for (int i = 0; i < 4; i++) a[i] = bm2[layer * DF + col];
        const float* w2 = Wm2 + (size_t)layer * DF * DF + col;
        for (int d = 0; d < DF; d++) {
            float w = w2[d * DF];
#pragma unroll
            for (int i = 0; i < 4; i++)
                a[i] = fmaf(sA1[(half * 4 + i) * DF + d], w, a[i]);
        }
        float* hout = (layer == 0) ? g_h1 : g_h2;
#pragma unroll
        for (int i = 0; i < 4; i++)
            hout[(size_t)(nb * NPB + half * 4 + i) * DF + col] = a[i];
    }
}

// ---------------- final bilinear score + sigmoid ----------------
__global__ void final_kernel(const int* __restrict__ etype_l,
                             const float* __restrict__ Wmatch,
                             const float* __restrict__ bmatch,
                             float* __restrict__ out) {
    __shared__ float ste[128];
    __shared__ float red[128];
    int b = blockIdx.x, d = threadIdx.x;
    int et = etype_l[b];
    ste[d] = g_h2[(BB + b) * DF + d];
    __syncthreads();
    float se = g_h2[b * DF + d];
    const float* wm = Wmatch + (size_t)(et * DF + d) * DF;
    float v = 0.f;
    for (int e = 0; e < DF; e++) v = fmaf(wm[e], ste[e], v);
    red[d] = se * v;
    __syncthreads();
    for (int s = 64; s > 0; s >>= 1) {
        if (d < s) red[d] += red[d + s];
        __syncthreads();
    }
    if (d == 0) {
        float score = red[0] + bmatch[et];
        out[b] = 1.f / (1.f + expf(-score));
    }
}

extern "C" void kernel_launch(void* const* d_in, const int* in_sizes, int n_in,
                              void* d_out, int out_size) {
    const int*   src_idx   = (const int*)d_in[0];
    const int*   tgt_idx   = (const int*)d_in[1];
    const float* cut_time  = (const float*)d_in[2];
    const int*   etype_l   = (const int*)d_in[5];
    const int*   ngh_node2 = (const int*)d_in[6];
    const int*   ngh_eidx2 = (const int*)d_in[7];
    const float* ngh_t2    = (const float*)d_in[8];
    const int*   ngh_et2   = (const int*)d_in[9];
    const int*   ngh_node1 = (const int*)d_in[11];
    const int*   ngh_eidx1 = (const int*)d_in[12];
    const float* ngh_t1    = (const float*)d_in[13];
    const int*   ngh_et1   = (const int*)d_in[14];
    const float* n_feat    = (const float*)d_in[16];
    const float* e_feat    = (const float*)d_in[17];
    const float* mem_tab   = (const float*)d_in[18];
    const float* freq      = (const float*)d_in[19];
    const float* phase     = (const float*)d_in[20];
    const float* Wq        = (const float*)d_in[21];
    const float* Wk        = (const float*)d_in[22];
    const float* Wv        = (const float*)d_in[23];
    const float* Wo        = (const float*)d_in[24];
    const float* Wm1       = (const float*)d_in[25];
    const float* bm1       = (const float*)d_in[26];
    const float* Wm2       = (const float*)d_in[27];
    const float* bm2       = (const float*)d_in[28];
    const float* Wrel      = (const float*)d_in[29];
    const float* Wmatch    = (const float*)d_in[30];
    const float* bmatch    = (const float*)d_in[31];
    float* out = (float*)d_out;

    const int GEMM_SMEM = 3 * BUFB;              // 110592 B
    const int ATTN_SMEM = 23912 * 4;             // 95648 B
    cudaFuncSetAttribute(gemm_kernel, cudaFuncAttributeMaxDynamicSharedMemorySize, GEMM_SMEM);
    cudaFuncSetAttribute(attn_kernel, cudaFuncAttributeMaxDynamicSharedMemorySize, ATTN_SMEM);

    pre_weights<<<2 * NOUT, 128>>>(Wrel, Wk, Wv);
    pre_misc<<<770, 384>>>(Wq, Wo, Wm1, phase);

    // ---- layer 0: 10240 query nodes, 409600 neighbor rows ----
    gather_kernel<<<R1 / 4, 512>>>(0, ngh_node1, ngh_eidx1, ngh_t1, ngh_et1,
                                   ngh_t2, n_feat, mem_tab, e_feat, freq, phase);
    gemm_kernel<<<dim3(NOUT / 128, R1 / 128), 256, GEMM_SMEM>>>(0);
    attn_kernel<<<R2 / NPB, 256, ATTN_SMEM>>>(0, ngh_node1, ngh_node2, (const int*)0,
                                              n_feat, mem_tab, Wq, Wm1, bm1, Wm2, bm2);

    // ---- layer 1: 256 query nodes, 10240 neighbor rows ----
    gather_kernel<<<R2 / 4, 512>>>(1, ngh_node2, ngh_eidx2, ngh_t2, ngh_et2,
                                   cut_time, n_feat, mem_tab, e_feat, freq, phase);
    gemm_kernel<<<dim3(NOUT / 128, R2 / 128), 256, GEMM_SMEM>>>(1);
    attn_kernel<<<256 / NPB, 256, ATTN_SMEM>>>(1, ngh_node2, src_idx, tgt_idx,
                                               n_feat, mem_tab, Wq, Wm1, bm1, Wm2, bm2);

    final_kernel<<<BB, 128>>>(etype_l, Wmatch, bmatch, out);
}

// round 10
// speedup vs baseline: 1.3463x; 1.3463x over previous
#include <cuda_runtime.h>
#include <cuda_fp16.h>
#include <math.h>
#include <stdint.h>

#define KNB 40
#define DF 128
#define MDIM 384
#define HH 4
#define DHD 96
#define BB 128
#define R1 409600
#define R2 10240
#define KX 512
#define NOUT 768
#define NPB 8
#define KV2 776              // padded halves per KV row in smem
#define KVBUFH (KNB * KV2)   // 31040 halves per buffer

// ---------------- scratch (__device__ globals, no allocation) ----------------
__device__ __align__(16) __half g_X[(size_t)R1 * KX];          // gathered features (fp16)
__device__ __align__(16) __half g_Wt[2 * NOUT * KX];           // fused K|V weights [l][n][k]
__device__ __align__(16) __half g_KV[(size_t)R1 * NOUT];       // K|V projections (fp16)
__device__ float g_qconst[2][384];
__device__ float g_WoM1[2][384 * 128];
__device__ float g_h1[R2 * DF];
__device__ float g_h2[256 * DF];

// ---------------- helpers ----------------
__device__ __forceinline__ uint32_t smem_u32(const void* p) {
    return (uint32_t)__cvta_generic_to_shared((void*)p);
}
#define CP_ASYNC16(dst, src) \
    asm volatile("cp.async.cg.shared.global [%0], [%1], 16;" :: "r"(dst), "l"(src) : "memory")
#define CP_COMMIT() asm volatile("cp.async.commit_group;" ::: "memory")
#define CP_WAIT(n)  asm volatile("cp.async.wait_group %0;" :: "n"(n) : "memory")
#define LDSM_X4(d0, d1, d2, d3, addr) \
    asm volatile("ldmatrix.sync.aligned.m8n8.x4.shared.b16 {%0,%1,%2,%3}, [%4];" \
        : "=r"(d0), "=r"(d1), "=r"(d2), "=r"(d3) : "r"(addr))

__device__ __forceinline__ void mma16816(float* c, uint32_t a0, uint32_t a1,
                                         uint32_t a2, uint32_t a3,
                                         uint32_t b0, uint32_t b1) {
    asm volatile(
        "mma.sync.aligned.m16n8k16.row.col.f32.f16.f16.f32 "
        "{%0,%1,%2,%3}, {%4,%5,%6,%7}, {%8,%9}, {%0,%1,%2,%3};"
        : "+f"(c[0]), "+f"(c[1]), "+f"(c[2]), "+f"(c[3])
        : "r"(a0), "r"(a1), "r"(a2), "r"(a3), "r"(b0), "r"(b1));
}

// FMA-pipe cos: quadrant range reduction + polys on [-pi/4, pi/4].
// Accurate to ~1e-5 for |x| <= ~2000 rad; fp16 downstream dominates error.
__device__ __forceinline__ float fcospoly(float x) {
    float n = rintf(x * 0.6366197723675814f);          // x * 2/pi
    float r = fmaf(n, -1.5707963705062866e0f, x);      // hi of pi/2
    r = fmaf(n, 4.3711388286737929e-8f, r);            // lo correction
    int q = ((int)n) & 3;
    float r2 = r * r;
    float pc = fmaf(r2, fmaf(r2, fmaf(r2, -1.388888889e-3f, 4.166666667e-2f), -0.5f), 1.0f);
    float ps = r * fmaf(r2, fmaf(r2, fmaf(r2, -1.984126984e-4f, 8.333333333e-3f), -1.666666667e-1f), 1.0f);
    float v = (q & 1) ? ps : pc;
    return ((q + 1) & 2) ? -v : v;
}

// ------------- precompute: fused transposed K|V weights (fp16) ---------------
__global__ void pre_weights(const float* __restrict__ Wrel,
                            const float* __restrict__ Wk,
                            const float* __restrict__ Wv) {
    int l = blockIdx.x / NOUT;
    int n = blockIdx.x % NOUT;
    int t = threadIdx.x;   // 128
    const float* Ws = ((n < MDIM) ? Wk : Wv) + (size_t)l * MDIM * MDIM;
    int nc = (n < MDIM) ? n : n - MDIM;
    const float* wr0 = Wrel + ((size_t)(l * 2 + 0) * DF + t) * DF;
    const float* wr1 = Wrel + ((size_t)(l * 2 + 1) * DF + t) * DF;
    float v0 = 0.f, v1 = 0.f;
    for (int j = 0; j < DF; j++) {
        float w = Ws[(size_t)j * MDIM + nc];
        v0 = fmaf(wr0[j], w, v0);
        v1 = fmaf(wr1[j], w, v1);
    }
    size_t base = ((size_t)l * NOUT + n) * KX;
    g_Wt[base + t]        = __float2half_rn(v0);
    g_Wt[base + DF + t]   = __float2half_rn(v1);
    g_Wt[base + 256 + t]  = __float2half_rn(Ws[(size_t)(DF + t) * MDIM + nc]);
    g_Wt[base + 384 + t]  = __float2half_rn(Ws[(size_t)(256 + t) * MDIM + nc]);
}

// ---------------- precompute: qconst + Wo@Wm1 ----------------
__global__ void pre_misc(const float* __restrict__ Wq,
                         const float* __restrict__ Wo,
                         const float* __restrict__ Wm1,
                         const float* __restrict__ phase) {
    int bid = blockIdx.x;          // 770 = 2*(384+1)
    int l = bid / 385;
    int r = bid % 385;
    int tid = threadIdx.x;         // 384
    if (r == 384) {
        float acc = 0.f;
        for (int j = 0; j < 128; j++)
            acc = fmaf(cosf(phase[j]), Wq[(size_t)l * MDIM * MDIM + (256 + j) * MDIM + tid], acc);
        g_qconst[l][tid] = acc;
    } else if (tid < 128) {
        float acc = 0.f;
        for (int j = 0; j < MDIM; j++)
            acc = fmaf(Wo[(size_t)l * MDIM * MDIM + r * MDIM + j],
                       Wm1[(size_t)(l * 512 + j) * 128 + tid], acc);
        g_WoM1[l][r * 128 + tid] = acc;
    }
}

// ---------------- gather: build X rows (fp16), 4 rows per CTA ----------------
__global__ void gather_kernel(int layer, const int* __restrict__ nghNode,
                              const int* __restrict__ nghEidx,
                              const float* __restrict__ nghT,
                              const int* __restrict__ nghEt,
                              const float* __restrict__ parentT,
                              const float* __restrict__ n_feat,
                              const float* __restrict__ mem_tab,
                              const float* __restrict__ e_feat,
                              const float* __restrict__ freq,
                              const float* __restrict__ phase) {
    int r = blockIdx.x * 4 + (threadIdx.x >> 7);
    int j = threadIdx.x & 127;
    int node = nghNode[r];
    int eidx = nghEidx[r];
    int et = nghEt[r];
    int p = r / KNB;
    float tq = (layer == 0) ? parentT[p] : parentT[p & (BB - 1)];
    float dt = tq - nghT[r];
    float nf = (layer == 0)
        ? n_feat[(size_t)node * DF + j] + mem_tab[(size_t)node * DF + j]
        : g_h1[(size_t)r * DF + j];
    float ef = e_feat[(size_t)eidx * DF + j];
    float tf = fcospoly(fmaf(dt, freq[j], phase[j]));
    size_t base = (size_t)r * KX;
    g_X[base + j]        = __float2half_rn((et == 0) ? nf : 0.f);
    g_X[base + DF + j]   = __float2half_rn((et == 1) ? nf : 0.f);
    g_X[base + 256 + j]  = __float2half_rn(ef);
    g_X[base + 384 + j]  = __float2half_rn(tf);
}

// ---------------- HMMA GEMM: KV = X @ Wt' ----------------
// CTA tile 128x128, K=512 in 8 chunks of 64, 3-stage cp.async pipeline,
// one barrier per chunk. 8 warps (4M x 2N), warp tile 32x64.
// Grid: (N-blocks, M-blocks) -> N fastest so X tiles hit L2 across N sweep.
#define STR 72                         // padded smem stride in halves (144B rows)
#define ABYTES (128 * STR * 2)         // 18432
#define BUFB   (2 * ABYTES)            // 36864 per stage (A + B)
__global__ __launch_bounds__(256, 2)
void gemm_kernel(int layer) {
    extern __shared__ char smem[];
    const uint32_t smem_base = smem_u32(smem);
    const int tid = threadIdx.x;
    const int wid = tid >> 5;
    const int lane = tid & 31;
    const int n0 = blockIdx.x * 128;
    const int m0 = blockIdx.y * 128;
    const int wm = wid >> 1;           // 0..3
    const int wn = wid & 1;            // 0..1
    const int mbase = wm * 32;
    const int nbase = wn * 64;

    const int lrow = lane & 15;                      // A: row within 16
    const int akh  = (lane >> 4) * 8;                // A: k-half select
    const int brow = (lane & 7) + ((lane >> 4) * 8); // B: row within 16
    const int bkh  = ((lane >> 3) & 1) * 8;          // B: k-half select

    const __half* gW = g_Wt + (size_t)layer * NOUT * KX;

    float acc[2][8][4];
#pragma unroll
    for (int mt = 0; mt < 2; mt++)
#pragma unroll
        for (int nt = 0; nt < 8; nt++)
#pragma unroll
            for (int q = 0; q < 4; q++) acc[mt][nt][q] = 0.f;

    auto stage = [&](int c) {
        const int kb = c * 64;
        const uint32_t sbase = smem_base + (c % 3) * BUFB;
#pragma unroll
        for (int it = 0; it < 8; it++) {
            int i = tid + it * 256;                // 0..2047
            int isB = i >> 10;
            int j = i & 1023;
            int row = j >> 3, seg = j & 7;
            uint32_t dst = sbase + isB * ABYTES + (uint32_t)(row * STR + seg * 8) * 2;
            const __half* src = isB ? (gW + (size_t)(n0 + row) * KX + kb + seg * 8)
                                    : (g_X + (size_t)(m0 + row) * KX + kb + seg * 8);
            CP_ASYNC16(dst, src);
        }
        CP_COMMIT();
    };

    stage(0);
    stage(1);
    for (int c = 0; c < 8; c++) {
        if (c < 7) CP_WAIT(1); else CP_WAIT(0);
        __syncthreads();
        const uint32_t sA = smem_base + (c % 3) * BUFB;
        const uint32_t sB = sA + ABYTES;
#pragma unroll
        for (int ks = 0; ks < 4; ks++) {
            const int k16 = ks * 16;
            uint32_t bf[8][2];
#pragma unroll
            for (int nt2 = 0; nt2 < 4; nt2++) {
                uint32_t d0, d1, d2, d3;
                uint32_t addr = sB + (uint32_t)((nbase + nt2 * 16 + brow) * STR + k16 + bkh) * 2;
                LDSM_X4(d0, d1, d2, d3, addr);
                bf[nt2 * 2][0] = d0; bf[nt2 * 2][1] = d1;
                bf[nt2 * 2 + 1][0] = d2; bf[nt2 * 2 + 1][1] = d3;
            }
#pragma unroll
            for (int mt = 0; mt < 2; mt++) {
                uint32_t a0, a1, a2, a3;
                uint32_t addr = sA + (uint32_t)((mbase + mt * 16 + lrow) * STR + k16 + akh) * 2;
                LDSM_X4(a0, a1, a2, a3, addr);
#pragma unroll
                for (int nt = 0; nt < 8; nt++)
                    mma16816(acc[mt][nt], a0, a1, a2, a3, bf[nt][0], bf[nt][1]);
            }
        }
        // buffer (c+2)%3 is disjoint from c%3 (compute) and (c+1)%3 (in flight);
        // its chunk-(c-1) readers all passed this iteration's top barrier.
        if (c + 2 < 8) stage(c + 2);
    }

    // epilogue: write fp16 results
#pragma unroll
    for (int mt = 0; mt < 2; mt++) {
#pragma unroll
        for (int nt = 0; nt < 8; nt++) {
            int r = m0 + mbase + mt * 16 + (lane >> 2);
            int ccol = n0 + nbase + nt * 8 + (lane & 3) * 2;
            *(__half2*)(g_KV + (size_t)r * NOUT + ccol) =
                __floats2half2_rn(acc[mt][nt][0], acc[mt][nt][1]);
            *(__half2*)(g_KV + (size_t)(r + 8) * NOUT + ccol) =
                __floats2half2_rn(acc[mt][nt][2], acc[mt][nt][3]);
        }
    }
}

// ---------------- attention + MLP: 8 query nodes per CTA ----------------
// KV double-buffered in smem as fp16 via cp.async; warp-parallel softmax.
__global__ __launch_bounds__(256, 1)
void attn_kernel(int layer, const int* __restrict__ nghNode,
                 const int* __restrict__ srcA, const int* __restrict__ srcB,
                 const float* __restrict__ n_feat, const float* __restrict__ mem_tab,
                 const float* __restrict__ Wq, const float* __restrict__ Wm1,
                 const float* __restrict__ bm1, const float* __restrict__ Wm2,
                 const float* __restrict__ bm2) {
    extern __shared__ float sm[];
    __half* sKVh = (__half*)sm;              // 2 x 31040 halves = 31040 floats
    float* sSRC  = sm + 31040;               // 8*128
    float* sQ    = sm + 32064;               // 8*384
    float* sO    = sm + 35136;               // 8*384
    float* sS    = sm + 38208;               // 160
    float* sA1   = sm + 38368;               // 8*128
    int*   sMask = (int*)(sm + 39392);       // 40  (end 39432 floats)
    const int tid = threadIdx.x;
    const int nb = blockIdx.x;
    const uint32_t smem_base = smem_u32(sm);

    for (int i = tid; i < NPB * DF; i += 256) {
        int node = i >> 7, j = i & 127;
        int n = nb * NPB + node;
        int sid = (layer == 0) ? srcA[n] : ((n < BB) ? srcA[n] : srcB[n - BB]);
        sSRC[i] = n_feat[(size_t)sid * DF + j] + mem_tab[(size_t)sid * DF + j];
    }

    auto stageKV = [&](int i, int buf) {
        const __half* src = g_KV + (size_t)(nb * NPB + i) * KNB * NOUT;
        const uint32_t dbase = smem_base + buf * (KVBUFH * 2);
        for (int v = tid; v < KNB * 96; v += 256) {
            int row = v / 96, c8 = v % 96;
            CP_ASYNC16(dbase + (uint32_t)(row * KV2 + c8 * 8) * 2,
                       src + (size_t)row * NOUT + c8 * 8);
        }
        CP_COMMIT();
    };
    stageKV(0, 0);
    __syncthreads();

    // Q projection for all 8 nodes (weights loaded once, reused x8)
    {
        float acc0[NPB], acc1[NPB];
#pragma unroll
        for (int i = 0; i < NPB; i++) { acc0[i] = 0.f; acc1[i] = 0.f; }
        const float* wq = Wq + (size_t)layer * MDIM * MDIM;
        for (int m = 0; m < DF; m++) {
            float w0 = wq[(size_t)m * MDIM + tid];
            float w1 = (tid < 128) ? wq[(size_t)m * MDIM + 256 + tid] : 0.f;
#pragma unroll
            for (int i = 0; i < NPB; i++) {
                float x = sSRC[i * DF + m];
                acc0[i] = fmaf(x, w0, acc0[i]);
                acc1[i] = fmaf(x, w1, acc1[i]);
            }
        }
#pragma unroll
        for (int i = 0; i < NPB; i++) {
            sQ[i * MDIM + tid] = acc0[i] + g_qconst[layer][tid];
            if (tid < 128) sQ[i * MDIM + 256 + tid] = acc1[i] + g_qconst[layer][256 + tid];
        }
    }

    for (int i = 0; i < NPB; i++) {
        const int n = nb * NPB + i;
        if (i < 7) stageKV(i + 1, (i + 1) & 1);
        if (tid < KNB) sMask[tid] = (nghNode[n * KNB + tid] == 0) ? 1 : 0;
        if (i < 7) CP_WAIT(1); else CP_WAIT(0);
        __syncthreads();
        const __half* kvb = sKVh + (i & 1) * KVBUFH;
        // scores
        if (tid < HH * KNB) {
            int h = tid / KNB, row = tid % KNB;
            const __half2* kr2 = (const __half2*)(kvb + row * KV2 + h * DHD);
            const float* qk = sQ + i * MDIM + h * DHD;
            float s = 0.f;
#pragma unroll
            for (int d2 = 0; d2 < DHD / 2; d2++) {
                float2 kf = __half22float2(kr2[d2]);
                s = fmaf(qk[2 * d2], kf.x, s);
                s = fmaf(qk[2 * d2 + 1], kf.y, s);
            }
            s *= 0.10206207261596577f;   // 1/sqrt(96)
            if (sMask[row]) s = -1000000000.0f;
            sS[h * KNB + row] = s;
        }
        __syncthreads();
        // warp-parallel softmax: warp h handles head h
        if (tid < 128) {
            int h = tid >> 5, lane = tid & 31;
            float v0 = sS[h * KNB + lane];
            float v1 = (lane < 8) ? sS[h * KNB + 32 + lane] : -INFINITY;
            float mx = fmaxf(v0, v1);
#pragma unroll
            for (int o = 16; o > 0; o >>= 1)
                mx = fmaxf(mx, __shfl_xor_sync(0xFFFFFFFF, mx, o));
            float e0 = expf(v0 - mx);
            float e1 = (lane < 8) ? expf(v1 - mx) : 0.f;
            float sum = e0 + e1;
#pragma unroll
            for (int o = 16; o > 0; o >>= 1)
                sum += __shfl_xor_sync(0xFFFFFFFF, sum, o);
            float inv = 1.f / sum;
            sS[h * KNB + lane] = e0 * inv;
            if (lane < 8) sS[h * KNB + 32 + lane] = e1 * inv;
        }
        __syncthreads();
        // o = a @ V
        for (int cc = tid; cc < MDIM; cc += 256) {
            int h = cc / DHD;
            const float* a = sS + h * KNB;
            float o = 0.f;
            for (int k = 0; k < KNB; k++)
                o = fmaf(a[k], __half2float(kvb[k * KV2 + MDIM + cc]), o);
            sO[i * MDIM + cc] = o;
        }
        __syncthreads();
    }

    // MLP layer 1 (Wo folded into WoM1): 2 thread-halves x 4 nodes each
    {
        const int half = tid >> 7, col = tid & 127;
        float a[4];
#pragma unroll
        for (int i = 0; i < 4; i++) a[i] = bm1[layer * DF + col];
        const float* w1 = &g_WoM1[layer][col];
        for (int m = 0; m < MDIM; m++) {
            float w = w1[m * DF];
#pragma unroll
            for (int i = 0; i < 4; i++)
                a[i] = fmaf(sO[(half * 4 + i) * MDIM + m], w, a[i]);
        }
        const float* w1b = Wm1 + (size_t)(layer * 512 + MDIM) * DF + col;
        for (int m = 0; m < DF; m++) {
            float w = w1b[m * DF];
#pragma unroll
            for (int i = 0; i < 4; i++)
                a[i] = fmaf(sSRC[(half * 4 + i) * DF + m], w, a[i]);
        }
#pragma unroll
        for (int i = 0; i < 4; i++) sA1[(half * 4 + i) * DF + col] = fmaxf(a[i], 0.f);
    }
    __syncthreads();
    {
        const int half = tid >> 7, col = tid & 127;
        float a[4];
#pragma unroll
        for (int i = 0; i < 4; i++) a[i] = bm2[layer * DF + col];
        const float* w2 = Wm2 + (size_t)layer * DF * DF + col;
        for (int d = 0; d < DF; d++) {
            float w = w2[d * DF];
#pragma unroll
            for (int i = 0; i < 4; i++)
                a[i] = fmaf(sA1[(half * 4 + i) * DF + d], w, a[i]);
        }
        float* hout = (layer == 0) ? g_h1 : g_h2;
#pragma unroll
        for (int i = 0; i < 4; i++)
            hout[(size_t)(nb * NPB + half * 4 + i) * DF + col] = a[i];
    }
}

// ---------------- final bilinear score + sigmoid ----------------
__global__ void final_kernel(const int* __restrict__ etype_l,
                             const float* __restrict__ Wmatch,
                             const float* __restrict__ bmatch,
                             float* __restrict__ out) {
    __shared__ float ste[128];
    __shared__ float red[128];
    int b = blockIdx.x, d = threadIdx.x;
    int et = etype_l[b];
    ste[d] = g_h2[(BB + b) * DF + d];
    __syncthreads();
    float se = g_h2[b * DF + d];
    const float* wm = Wmatch + (size_t)(et * DF + d) * DF;
    float v = 0.f;
    for (int e = 0; e < DF; e++) v = fmaf(wm[e], ste[e], v);
    red[d] = se * v;
    __syncthreads();
    for (int s = 64; s > 0; s >>= 1) {
        if (d < s) red[d] += red[d + s];
        __syncthreads();
    }
    if (d == 0) {
        float score = red[0] + bmatch[et];
        out[b] = 1.f / (1.f + expf(-score));
    }
}

extern "C" void kernel_launch(void* const* d_in, const int* in_sizes, int n_in,
                              void* d_out, int out_size) {
    const int*   src_idx   = (const int*)d_in[0];
    const int*   tgt_idx   = (const int*)d_in[1];
    const float* cut_time  = (const float*)d_in[2];
    const int*   etype_l   = (const int*)d_in[5];
    const int*   ngh_node2 = (const int*)d_in[6];
    const int*   ngh_eidx2 = (const int*)d_in[7];
    const float* ngh_t2    = (const float*)d_in[8];
    const int*   ngh_et2   = (const int*)d_in[9];
    const int*   ngh_node1 = (const int*)d_in[11];
    const int*   ngh_eidx1 = (const int*)d_in[12];
    const float* ngh_t1    = (const float*)d_in[13];
    const int*   ngh_et1   = (const int*)d_in[14];
    const float* n_feat    = (const float*)d_in[16];
    const float* e_feat    = (const float*)d_in[17];
    const float* mem_tab   = (const float*)d_in[18];
    const float* freq      = (const float*)d_in[19];
    const float* phase     = (const float*)d_in[20];
    const float* Wq        = (const float*)d_in[21];
    const float* Wk        = (const float*)d_in[22];
    const float* Wv        = (const float*)d_in[23];
    const float* Wo        = (const float*)d_in[24];
    const float* Wm1       = (const float*)d_in[25];
    const float* bm1       = (const float*)d_in[26];
    const float* Wm2       = (const float*)d_in[27];
    const float* bm2       = (const float*)d_in[28];
    const float* Wrel      = (const float*)d_in[29];
    const float* Wmatch    = (const float*)d_in[30];
    const float* bmatch    = (const float*)d_in[31];
    float* out = (float*)d_out;

    const int GEMM_SMEM = 3 * BUFB;              // 110592 B
    const int ATTN_SMEM = 39432 * 4;             // 157728 B
    cudaFuncSetAttribute(gemm_kernel, cudaFuncAttributeMaxDynamicSharedMemorySize, GEMM_SMEM);
    cudaFuncSetAttribute(attn_kernel, cudaFuncAttributeMaxDynamicSharedMemorySize, ATTN_SMEM);

    pre_weights<<<2 * NOUT, 128>>>(Wrel, Wk, Wv);
    pre_misc<<<770, 384>>>(Wq, Wo, Wm1, phase);

    // ---- layer 0: 10240 query nodes, 409600 neighbor rows ----
    gather_kernel<<<R1 / 4, 512>>>(0, ngh_node1, ngh_eidx1, ngh_t1, ngh_et1,
                                   ngh_t2, n_feat, mem_tab, e_feat, freq, phase);
    gemm_kernel<<<dim3(NOUT / 128, R1 / 128), 256, GEMM_SMEM>>>(0);
    attn_kernel<<<R2 / NPB, 256, ATTN_SMEM>>>(0, ngh_node1, ngh_node2, (const int*)0,
                                              n_feat, mem_tab, Wq, Wm1, bm1, Wm2, bm2);

    // ---- layer 1: 256 query nodes, 10240 neighbor rows ----
    gather_kernel<<<R2 / 4, 512>>>(1, ngh_node2, ngh_eidx2, ngh_t2, ngh_et2,
                                   cut_time, n_feat, mem_tab, e_feat, freq, phase);
    gemm_kernel<<<dim3(NOUT / 128, R2 / 128), 256, GEMM_SMEM>>>(1);
    attn_kernel<<<256 / NPB, 256, ATTN_SMEM>>>(1, ngh_node2, src_idx, tgt_idx,
                                               n_feat, mem_tab, Wq, Wm1, bm1, Wm2, bm2);

    final_kernel<<<BB, 128>>>(etype_l, Wmatch, bmatch, out);
}

// round 11
// speedup vs baseline: 1.4815x; 1.1004x over previous
#include <cuda_runtime.h>
#include <cuda_fp16.h>
#include <math.h>
#include <stdint.h>

#define KNB 40
#define DF 128
#define MDIM 384
#define HH 4
#define DHD 96
#define BB 128
#define R1 409600
#define R2 10240
#define KX2 384              // packed K: [nf | ef | tf]
#define NOUT 768
#define NPB 8
#define KV2 776              // padded halves per KV row in smem
#define KVBUFH (KNB * KV2)   // 31040 halves per buffer

// ---------------- scratch (__device__ globals, no allocation) ----------------
// zero-initialized at module load; gap rows (fixed positions per input set)
// are never written and stay zero.
__device__ __align__(16) __half g_X[(size_t)(R1 + 128) * KX2];
__device__ __align__(16) __half g_Wt[2 * 2 * NOUT * KX2];      // [l][et][n][k]
__device__ __align__(16) __half g_KV[(size_t)(R1 + 128) * NOUT];
__device__ float g_qconst[2][384];
__device__ float g_WoM1[2][384 * 128];
__device__ float g_h1[R2 * DF];
__device__ float g_h2[256 * DF];
__device__ int g_cnt[4];         // [layer][et] partition counters
__device__ int g_meta[2];        // tiles0 per layer
__device__ int g_perm1[R1];      // row -> packed position (layer 0)
__device__ int g_perm2[R2];      // row -> packed position (layer 1)

// ---------------- helpers ----------------
__device__ __forceinline__ uint32_t smem_u32(const void* p) {
    return (uint32_t)__cvta_generic_to_shared((void*)p);
}
#define CP_ASYNC16(dst, src) \
    asm volatile("cp.async.cg.shared.global [%0], [%1], 16;" :: "r"(dst), "l"(src) : "memory")
#define CP_COMMIT() asm volatile("cp.async.commit_group;" ::: "memory")
#define CP_WAIT(n)  asm volatile("cp.async.wait_group %0;" :: "n"(n) : "memory")
#define LDSM_X4(d0, d1, d2, d3, addr) \
    asm volatile("ldmatrix.sync.aligned.m8n8.x4.shared.b16 {%0,%1,%2,%3}, [%4];" \
        : "=r"(d0), "=r"(d1), "=r"(d2), "=r"(d3) : "r"(addr))

__device__ __forceinline__ void mma16816(float* c, uint32_t a0, uint32_t a1,
                                         uint32_t a2, uint32_t a3,
                                         uint32_t b0, uint32_t b1) {
    asm volatile(
        "mma.sync.aligned.m16n8k16.row.col.f32.f16.f16.f32 "
        "{%0,%1,%2,%3}, {%4,%5,%6,%7}, {%8,%9}, {%0,%1,%2,%3};"
        : "+f"(c[0]), "+f"(c[1]), "+f"(c[2]), "+f"(c[3])
        : "r"(a0), "r"(a1), "r"(a2), "r"(a3), "r"(b0), "r"(b1));
}

// FMA-pipe cos: quadrant range reduction + polys on [-pi/4, pi/4].
__device__ __forceinline__ float fcospoly(float x) {
    float n = rintf(x * 0.6366197723675814f);          // x * 2/pi
    float r = fmaf(n, -1.5707963705062866e0f, x);      // hi of pi/2
    r = fmaf(n, 4.3711388286737929e-8f, r);            // lo correction
    int q = ((int)n) & 3;
    float r2 = r * r;
    float pc = fmaf(r2, fmaf(r2, fmaf(r2, -1.388888889e-3f, 4.166666667e-2f), -0.5f), 1.0f);
    float ps = r * fmaf(r2, fmaf(r2, fmaf(r2, -1.984126984e-4f, 8.333333333e-3f), -1.666666667e-1f), 1.0f);
    float v = (q & 1) ? ps : pc;
    return ((q + 1) & 2) ? -v : v;
}

// ---------------- partition: rank rows by etype (warp-aggregated atomics) ----
__global__ void reset_kernel() {
    if (threadIdx.x < 4) g_cnt[threadIdx.x] = 0;
}
__global__ void partA_kernel(const int* __restrict__ et_arr, int* __restrict__ rank,
                             int cb) {
    int r = blockIdx.x * 256 + threadIdx.x;
    int et = (et_arr[r] != 0) ? 1 : 0;
    const unsigned m = 0xFFFFFFFFu;
    unsigned b1 = __ballot_sync(m, et == 1);
    unsigned b0 = ~b1;
    int lane = threadIdx.x & 31;
    unsigned lower = (1u << lane) - 1u;
    int base0 = 0, base1 = 0;
    int l0 = __ffs(b0) - 1, l1 = __ffs(b1) - 1;
    if (b0 && lane == l0) base0 = atomicAdd(&g_cnt[cb + 0], __popc(b0));
    if (b1 && lane == l1) base1 = atomicAdd(&g_cnt[cb + 1], __popc(b1));
    if (b0) base0 = __shfl_sync(m, base0, l0);
    if (b1) base1 = __shfl_sync(m, base1, l1);
    rank[r] = et ? (base1 + __popc(b1 & lower)) : (base0 + __popc(b0 & lower));
}
__global__ void partB_kernel(const int* __restrict__ et_arr, int* __restrict__ perm,
                             int cb, int layer) {
    int r = blockIdx.x * 256 + threadIdx.x;
    int c0 = g_cnt[cb + 0];
    int tiles0 = (c0 + 127) >> 7;
    int et = (et_arr[r] != 0) ? 1 : 0;
    int rk = perm[r];                  // in-place: rank -> position
    perm[r] = et ? (tiles0 * 128 + rk) : rk;
    if (r == 0) g_meta[layer] = tiles0;
}

// ------------- precompute: fused transposed K|V weights per etype (fp16) -----
// g_Wt[l][et][n][k]: k<128 -> (Wrel[l][et] @ W)[k][nc]; [128,256) -> W rows
// 128..255 (edge); [256,384) -> W rows 256..383 (time). n<384: Wk col; else Wv.
__global__ void pre_weights(const float* __restrict__ Wrel,
                            const float* __restrict__ Wk,
                            const float* __restrict__ Wv) {
    int b = blockIdx.x;                  // 2*2*NOUT
    int l = b / (2 * NOUT);
    int rem = b % (2 * NOUT);
    int et = rem / NOUT;
    int n = rem % NOUT;
    int t = threadIdx.x;                 // 128
    const float* Ws = ((n < MDIM) ? Wk : Wv) + (size_t)l * MDIM * MDIM;
    int nc = (n < MDIM) ? n : n - MDIM;
    const float* wr = Wrel + ((size_t)(l * 2 + et) * DF + t) * DF;
    float v = 0.f;
    for (int j = 0; j < DF; j++)
        v = fmaf(wr[j], Ws[(size_t)j * MDIM + nc], v);
    size_t base = ((size_t)((l * 2 + et) * NOUT) + n) * KX2;
    g_Wt[base + t]        = __float2half_rn(v);
    g_Wt[base + 128 + t]  = __float2half_rn(Ws[(size_t)(DF + t) * MDIM + nc]);
    g_Wt[base + 256 + t]  = __float2half_rn(Ws[(size_t)(256 + t) * MDIM + nc]);
}

// ---------------- precompute: qconst + Wo@Wm1 ----------------
__global__ void pre_misc(const float* __restrict__ Wq,
                         const float* __restrict__ Wo,
                         const float* __restrict__ Wm1,
                         const float* __restrict__ phase) {
    int bid = blockIdx.x;          // 770 = 2*(384+1)
    int l = bid / 385;
    int r = bid % 385;
    int tid = threadIdx.x;         // 384
    if (r == 384) {
        float acc = 0.f;
        for (int j = 0; j < 128; j++)
            acc = fmaf(cosf(phase[j]), Wq[(size_t)l * MDIM * MDIM + (256 + j) * MDIM + tid], acc);
        g_qconst[l][tid] = acc;
    } else if (tid < 128) {
        float acc = 0.f;
        for (int j = 0; j < MDIM; j++)
            acc = fmaf(Wo[(size_t)l * MDIM * MDIM + r * MDIM + j],
                       Wm1[(size_t)(l * 512 + j) * 128 + tid], acc);
        g_WoM1[l][r * 128 + tid] = acc;
    }
}

// ---------------- gather: build packed X rows (fp16, 2 cols/thread) ----------
__global__ void gather_kernel(int layer, const int* __restrict__ nghNode,
                              const int* __restrict__ nghEidx,
                              const float* __restrict__ nghT,
                              const int* __restrict__ perm,
                              const float* __restrict__ parentT,
                              const float* __restrict__ n_feat,
                              const float* __restrict__ mem_tab,
                              const float* __restrict__ e_feat,
                              const float* __restrict__ freq,
                              const float* __restrict__ phase) {
    int rg = threadIdx.x >> 6;          // 0..3 rows per CTA
    int u  = threadIdx.x & 63;          // column pair
    int r = blockIdx.x * 4 + rg;
    int node = nghNode[r];
    int eidx = nghEidx[r];
    int pos = perm[r];
    int p = r / KNB;
    float tq = (layer == 0) ? parentT[p] : parentT[p & (BB - 1)];
    float dt = tq - nghT[r];
    int j = 2 * u;
    float2 nf2;
    if (layer == 0) {
        float2 a = *(const float2*)(n_feat + (size_t)node * DF + j);
        float2 b = *(const float2*)(mem_tab + (size_t)node * DF + j);
        nf2 = make_float2(a.x + b.x, a.y + b.y);
    } else {
        nf2 = *(const float2*)(g_h1 + (size_t)r * DF + j);
    }
    float2 ef2 = *(const float2*)(e_feat + (size_t)eidx * DF + j);
    float2 fr2 = *(const float2*)(freq + j);
    float2 ph2 = *(const float2*)(phase + j);
    float tfx = fcospoly(fmaf(dt, fr2.x, ph2.x));
    float tfy = fcospoly(fmaf(dt, fr2.y, ph2.y));
    __half2* dst = (__half2*)(g_X + (size_t)pos * KX2);
    dst[u]        = __floats2half2_rn(nf2.x, nf2.y);
    dst[64 + u]   = __floats2half2_rn(ef2.x, ef2.y);
    dst[128 + u]  = __floats2half2_rn(tfx, tfy);
}

// ---------------- HMMA GEMM: KV = X @ Wt[et]' ----------------
// CTA tile 128x128, K=384 in 6 chunks of 64, 3-stage cp.async pipeline,
// one barrier per chunk. 8 warps (4M x 2N), warp tile 32x64.
// Weight set selected per M-tile: et = (blockIdx.y >= tiles0).
#define STR 72                         // padded smem stride in halves (144B rows)
#define ABYTES (128 * STR * 2)         // 18432
#define BUFB   (2 * ABYTES)            // 36864 per stage (A + B)
#define NCHK   (KX2 / 64)              // 6
__global__ __launch_bounds__(256, 2)
void gemm_kernel(int layer) {
    extern __shared__ char smem[];
    const uint32_t smem_base = smem_u32(smem);
    const int tid = threadIdx.x;
    const int wid = tid >> 5;
    const int lane = tid & 31;
    const int n0 = blockIdx.x * 128;
    const int m0 = blockIdx.y * 128;
    const int wm = wid >> 1;           // 0..3
    const int wn = wid & 1;            // 0..1
    const int mbase = wm * 32;
    const int nbase = wn * 64;

    const int lrow = lane & 15;                      // A: row within 16
    const int akh  = (lane >> 4) * 8;                // A: k-half select
    const int brow = (lane & 7) + ((lane >> 4) * 8); // B: row within 16
    const int bkh  = ((lane >> 3) & 1) * 8;          // B: k-half select

    const int tiles0 = g_meta[layer];
    const int et = ((int)blockIdx.y >= tiles0) ? 1 : 0;
    const __half* gW = g_Wt + (size_t)((layer * 2 + et) * NOUT) * KX2;

    float acc[2][8][4];
#pragma unroll
    for (int mt = 0; mt < 2; mt++)
#pragma unroll
        for (int nt = 0; nt < 8; nt++)
#pragma unroll
            for (int q = 0; q < 4; q++) acc[mt][nt][q] = 0.f;

    auto stage = [&](int c) {
        const int kb = c * 64;
        const uint32_t sbase = smem_base + (c % 3) * BUFB;
#pragma unroll
        for (int it = 0; it < 8; it++) {
            int i = tid + it * 256;                // 0..2047
            int isB = i >> 10;
            int j = i & 1023;
            int row = j >> 3, seg = j & 7;
            uint32_t dst = sbase + isB * ABYTES + (uint32_t)(row * STR + seg * 8) * 2;
            const __half* src = isB ? (gW + (size_t)(n0 + row) * KX2 + kb + seg * 8)
                                    : (g_X + (size_t)(m0 + row) * KX2 + kb + seg * 8);
            CP_ASYNC16(dst, src);
        }
        CP_COMMIT();
    };

    stage(0);
    stage(1);
    for (int c = 0; c < NCHK; c++) {
        if (c < NCHK - 1) CP_WAIT(1); else CP_WAIT(0);
        __syncthreads();
        const uint32_t sA = smem_base + (c % 3) * BUFB;
        const uint32_t sB = sA + ABYTES;
#pragma unroll
        for (int ks = 0; ks < 4; ks++) {
            const int k16 = ks * 16;
            uint32_t bf[8][2];
#pragma unroll
            for (int nt2 = 0; nt2 < 4; nt2++) {
                uint32_t d0, d1, d2, d3;
                uint32_t addr = sB + (uint32_t)((nbase + nt2 * 16 + brow) * STR + k16 + bkh) * 2;
                LDSM_X4(d0, d1, d2, d3, addr);
                bf[nt2 * 2][0] = d0; bf[nt2 * 2][1] = d1;
                bf[nt2 * 2 + 1][0] = d2; bf[nt2 * 2 + 1][1] = d3;
            }
#pragma unroll
            for (int mt = 0; mt < 2; mt++) {
                uint32_t a0, a1, a2, a3;
                uint32_t addr = sA + (uint32_t)((mbase + mt * 16 + lrow) * STR + k16 + akh) * 2;
                LDSM_X4(a0, a1, a2, a3, addr);
#pragma unroll
                for (int nt = 0; nt < 8; nt++)
                    mma16816(acc[mt][nt], a0, a1, a2, a3, bf[nt][0], bf[nt][1]);
            }
        }
        if (c + 2 < NCHK) stage(c + 2);
    }

    // epilogue: write fp16 results
#pragma unroll
    for (int mt = 0; mt < 2; mt++) {
#pragma unroll
        for (int nt = 0; nt < 8; nt++) {
            int r = m0 + mbase + mt * 16 + (lane >> 2);
            int ccol = n0 + nbase + nt * 8 + (lane & 3) * 2;
            *(__half2*)(g_KV + (size_t)r * NOUT + ccol) =
                __floats2half2_rn(acc[mt][nt][0], acc[mt][nt][1]);
            *(__half2*)(g_KV + (size_t)(r + 8) * NOUT + ccol) =
                __floats2half2_rn(acc[mt][nt][2], acc[mt][nt][3]);
        }
    }
}

// ---------------- attention + MLP: 8 query nodes per CTA ----------------
// KV double-buffered in smem as fp16 via cp.async (perm-indirected rows).
__global__ __launch_bounds__(256, 1)
void attn_kernel(int layer, const int* __restrict__ nghNode,
                 const int* __restrict__ perm,
                 const int* __restrict__ srcA, const int* __restrict__ srcB,
                 const float* __restrict__ n_feat, const float* __restrict__ mem_tab,
                 const float* __restrict__ Wq, const float* __restrict__ Wm1,
                 const float* __restrict__ bm1, const float* __restrict__ Wm2,
                 const float* __restrict__ bm2) {
    extern __shared__ float sm[];
    __half* sKVh = (__half*)sm;              // 2 x 31040 halves = 31040 floats
    float* sSRC  = sm + 31040;               // 8*128
    float* sQ    = sm + 32064;               // 8*384
    float* sO    = sm + 35136;               // 8*384
    float* sS    = sm + 38208;               // 160
    float* sA1   = sm + 38368;               // 8*128
    int*   sMask = (int*)(sm + 39392);       // 40  (end 39432 floats)
    const int tid = threadIdx.x;
    const int nb = blockIdx.x;
    const uint32_t smem_base = smem_u32(sm);

    for (int i = tid; i < NPB * DF; i += 256) {
        int node = i >> 7, j = i & 127;
        int n = nb * NPB + node;
        int sid = (layer == 0) ? srcA[n] : ((n < BB) ? srcA[n] : srcB[n - BB]);
        sSRC[i] = n_feat[(size_t)sid * DF + j] + mem_tab[(size_t)sid * DF + j];
    }

    auto stageKV = [&](int i, int buf) {
        const int nKNB = (nb * NPB + i) * KNB;
        const uint32_t dbase = smem_base + buf * (KVBUFH * 2);
        for (int v = tid; v < KNB * 96; v += 256) {
            int row = v / 96, c8 = v % 96;
            const __half* src = g_KV + (size_t)perm[nKNB + row] * NOUT + c8 * 8;
            CP_ASYNC16(dbase + (uint32_t)(row * KV2 + c8 * 8) * 2, src);
        }
        CP_COMMIT();
    };
    stageKV(0, 0);
    __syncthreads();

    // Q projection for all 8 nodes (weights loaded once, reused x8)
    {
        float acc0[NPB], acc1[NPB];
#pragma unroll
        for (int i = 0; i < NPB; i++) { acc0[i] = 0.f; acc1[i] = 0.f; }
        const float* wq = Wq + (size_t)layer * MDIM * MDIM;
        for (int m = 0; m < DF; m++) {
            float w0 = wq[(size_t)m * MDIM + tid];
            float w1 = (tid < 128) ? wq[(size_t)m * MDIM + 256 + tid] : 0.f;
#pragma unroll
            for (int i = 0; i < NPB; i++) {
                float x = sSRC[i * DF + m];
                acc0[i] = fmaf(x, w0, acc0[i]);
                acc1[i] = fmaf(x, w1, acc1[i]);
            }
        }
#pragma unroll
        for (int i = 0; i < NPB; i++) {
            sQ[i * MDIM + tid] = acc0[i] + g_qconst[layer][tid];
            if (tid < 128) sQ[i * MDIM + 256 + tid] = acc1[i] + g_qconst[layer][256 + tid];
        }
    }

    for (int i = 0; i < NPB; i++) {
        const int n = nb * NPB + i;
        if (i < 7) stageKV(i + 1, (i + 1) & 1);
        if (tid < KNB) sMask[tid] = (nghNode[n * KNB + tid] == 0) ? 1 : 0;
        if (i < 7) CP_WAIT(1); else CP_WAIT(0);
        __syncthreads();
        const __half* kvb = sKVh + (i & 1) * KVBUFH;
        // scores
        if (tid < HH * KNB) {
            int h = tid / KNB, row = tid % KNB;
            const __half2* kr2 = (const __half2*)(kvb + row * KV2 + h * DHD);
            const float* qk = sQ + i * MDIM + h * DHD;
            float s = 0.f;
#pragma unroll
            for (int d2 = 0; d2 < DHD / 2; d2++) {
                float2 kf = __half22float2(kr2[d2]);
                s = fmaf(qk[2 * d2], kf.x, s);
                s = fmaf(qk[2 * d2 + 1], kf.y, s);
            }
            s *= 0.10206207261596577f;   // 1/sqrt(96)
            if (sMask[row]) s = -1000000000.0f;
            sS[h * KNB + row] = s;
        }
        __syncthreads();
        // warp-parallel softmax: warp h handles head h
        if (tid < 128) {
            int h = tid >> 5, lane = tid & 31;
            float v0 = sS[h * KNB + lane];
            float v1 = (lane < 8) ? sS[h * KNB + 32 + lane] : -INFINITY;
            float mx = fmaxf(v0, v1);
#pragma unroll
            for (int o = 16; o > 0; o >>= 1)
                mx = fmaxf(mx, __shfl_xor_sync(0xFFFFFFFF, mx, o));
            float e0 = expf(v0 - mx);
            float e1 = (lane < 8) ? expf(v1 - mx) : 0.f;
            float sum = e0 + e1;
#pragma unroll
            for (int o = 16; o > 0; o >>= 1)
                sum += __shfl_xor_sync(0xFFFFFFFF, sum, o);
            float inv = 1.f / sum;
            sS[h * KNB + lane] = e0 * inv;
            if (lane < 8) sS[h * KNB + 32 + lane] = e1 * inv;
        }
        __syncthreads();
        // o = a @ V
        for (int cc = tid; cc < MDIM; cc += 256) {
            int h = cc / DHD;
            const float* a = sS + h * KNB;
            float o = 0.f;
            for (int k = 0; k < KNB; k++)
                o = fmaf(a[k], __half2float(kvb[k * KV2 + MDIM + cc]), o);
            sO[i * MDIM + cc] = o;
        }
        __syncthreads();
    }

    // MLP layer 1 (Wo folded into WoM1): 2 thread-halves x 4 nodes each
    {
        const int half = tid >> 7, col = tid & 127;
        float a[4];
#pragma unroll
        for (int i = 0; i < 4; i++) a[i] = bm1[layer * DF + col];
        const float* w1 = &g_WoM1[layer][col];
        for (int m = 0; m < MDIM; m++) {
            float w = w1[m * DF];
#pragma unroll
            for (int i = 0; i < 4; i++)
                a[i] = fmaf(sO[(half * 4 + i) * MDIM + m], w, a[i]);
        }
        const float* w1b = Wm1 + (size_t)(layer * 512 + MDIM) * DF + col;
        for (int m = 0; m < DF; m++) {
            float w = w1b[m * DF];
#pragma unroll
            for (int i = 0; i < 4; i++)
                a[i] = fmaf(sSRC[(half * 4 + i) * DF + m], w, a[i]);
        }
#pragma unroll
        for (int i = 0; i < 4; i++) sA1[(half * 4 + i) * DF + col] = fmaxf(a[i], 0.f);
    }
    __syncthreads();
    {
        const int half = tid >> 7, col = tid & 127;
        float a[4];
#pragma unroll
        for (int i = 0; i < 4; i++) a[i] = bm2[layer * DF + col];
        const float* w2 = Wm2 + (size_t)layer * DF * DF + col;
        for (int d = 0; d < DF; d++) {
            float w = w2[d * DF];
#pragma unroll
            for (int i = 0; i < 4; i++)
                a[i] = fmaf(sA1[(half * 4 + i) * DF + d], w, a[i]);
        }
        float* hout = (layer == 0) ? g_h1 : g_h2;
#pragma unroll
        for (int i = 0; i < 4; i++)
            hout[(size_t)(nb * NPB + half * 4 + i) * DF + col] = a[i];
    }
}

// ---------------- final bilinear score + sigmoid ----------------
__global__ void final_kernel(const int* __restrict__ etype_l,
                             const float* __restrict__ Wmatch,
                             const float* __restrict__ bmatch,
                             float* __restrict__ out) {
    __shared__ float ste[128];
    __shared__ float red[128];
    int b = blockIdx.x, d = threadIdx.x;
    int et = etype_l[b];
    ste[d] = g_h2[(BB + b) * DF + d];
    __syncthreads();
    float se = g_h2[b * DF + d];
    const float* wm = Wmatch + (size_t)(et * DF + d) * DF;
    float v = 0.f;
    for (int e = 0; e < DF; e++) v = fmaf(wm[e], ste[e], v);
    red[d] = se * v;
    __syncthreads();
    for (int s = 64; s > 0; s >>= 1) {
        if (d < s) red[d] += red[d + s];
        __syncthreads();
    }
    if (d == 0) {
        float score = red[0] + bmatch[et];
        out[b] = 1.f / (1.f + expf(-score));
    }
}

extern "C" void kernel_launch(void* const* d_in, const int* in_sizes, int n_in,
                              void* d_out, int out_size) {
    const int*   src_idx   = (const int*)d_in[0];
    const int*   tgt_idx   = (const int*)d_in[1];
    const float* cut_time  = (const float*)d_in[2];
    const int*   etype_l   = (const int*)d_in[5];
    const int*   ngh_node2 = (const int*)d_in[6];
    const int*   ngh_eidx2 = (const int*)d_in[7];
    const float* ngh_t2    = (const float*)d_in[8];
    const int*   ngh_et2   = (const int*)d_in[9];
    const int*   ngh_node1 = (const int*)d_in[11];
    const int*   ngh_eidx1 = (const int*)d_in[12];
    const float* ngh_t1    = (const float*)d_in[13];
    const int*   ngh_et1   = (const int*)d_in[14];
    const float* n_feat    = (const float*)d_in[16];
    const float* e_feat    = (const float*)d_in[17];
    const float* mem_tab   = (const float*)d_in[18];
    const float* freq      = (const float*)d_in[19];
    const float* phase     = (const float*)d_in[20];
    const float* Wq        = (const float*)d_in[21];
    const float* Wk        = (const float*)d_in[22];
    const float* Wv        = (const float*)d_in[23];
    const float* Wo        = (const float*)d_in[24];
    const float* Wm1       = (const float*)d_in[25];
    const float* bm1       = (const float*)d_in[26];
    const float* Wm2       = (const float*)d_in[27];
    const float* bm2       = (const float*)d_in[28];
    const float* Wrel      = (const float*)d_in[29];
    const float* Wmatch    = (const float*)d_in[30];
    const float* bmatch    = (const float*)d_in[31];
    float* out = (float*)d_out;

    int* d_perm1; cudaGetSymbolAddress((void**)&d_perm1, g_perm1);
    int* d_perm2; cudaGetSymbolAddress((void**)&d_perm2, g_perm2);

    const int GEMM_SMEM = 3 * BUFB;              // 110592 B
    const int ATTN_SMEM = 39432 * 4;             // 157728 B
    cudaFuncSetAttribute(gemm_kernel, cudaFuncAttributeMaxDynamicSharedMemorySize, GEMM_SMEM);
    cudaFuncSetAttribute(attn_kernel, cudaFuncAttributeMaxDynamicSharedMemorySize, ATTN_SMEM);

    reset_kernel<<<1, 32>>>();
    partA_kernel<<<R1 / 256, 256>>>(ngh_et1, d_perm1, 0);
    partB_kernel<<<R1 / 256, 256>>>(ngh_et1, d_perm1, 0, 0);
    partA_kernel<<<R2 / 256, 256>>>(ngh_et2, d_perm2, 2);
    partB_kernel<<<R2 / 256, 256>>>(ngh_et2, d_perm2, 2, 1);

    pre_weights<<<2 * 2 * NOUT, 128>>>(Wrel, Wk, Wv);
    pre_misc<<<770, 384>>>(Wq, Wo, Wm1, phase);

    // ---- layer 0: 10240 query nodes, 409600 neighbor rows ----
    gather_kernel<<<R1 / 4, 256>>>(0, ngh_node1, ngh_eidx1, ngh_t1, d_perm1,
                                   ngh_t2, n_feat, mem_tab, e_feat, freq, phase);
    gemm_kernel<<<dim3(NOUT / 128, R1 / 128 + 1), 256, GEMM_SMEM>>>(0);
    attn_kernel<<<R2 / NPB, 256, ATTN_SMEM>>>(0, ngh_node1, d_perm1,
                                              ngh_node2, (const int*)0,
                                              n_feat, mem_tab, Wq, Wm1, bm1, Wm2, bm2);

    // ---- layer 1: 256 query nodes, 10240 neighbor rows ----
    gather_kernel<<<R2 / 4, 256>>>(1, ngh_node2, ngh_eidx2, ngh_t2, d_perm2,
                                   cut_time, n_feat, mem_tab, e_feat, freq, phase);
    gemm_kernel<<<dim3(NOUT / 128, R2 / 128 + 1), 256, GEMM_SMEM>>>(1);
    attn_kernel<<<256 / NPB, 256, ATTN_SMEM>>>(1, ngh_node2, d_perm2,
                                               src_idx, tgt_idx,
                                               n_feat, mem_tab, Wq, Wm1, bm1, Wm2, bm2);

    final_kernel<<<BB, 128>>>(etype_l, Wmatch, bmatch, out);
}

// round 13
// speedup vs baseline: 1.7437x; 1.1770x over previous
#include <cuda_runtime.h>
#include <cuda_fp16.h>
#include <math.h>
#include <stdint.h>

#define KNB 40
#define DF 128
#define MDIM 384
#define HH 4
#define DHD 96
#define BB 128
#define R1 409600
#define R2 10240
#define KX2 384              // packed K: [nf | ef | tf]
#define NOUT 768
#define NPB 8
#define KV2 776              // padded halves per KV row in smem
#define KVBUFH (KNB * KV2)   // 31040 halves per buffer
#define QROWS (R2 + 256)     // 10496 query rows total (layer0 + layer1)

// ---------------- scratch (__device__ globals, no allocation) ----------------
__device__ __align__(16) __half g_X[(size_t)(R1 + 128) * KX2];
__device__ __align__(16) __half g_Wt[2 * 2 * NOUT * KX2];      // [l][et][n][k]
__device__ __align__(16) __half g_KV[(size_t)(R1 + 128) * NOUT];
__device__ __align__(16) __half g_Xq[(size_t)QROWS * DF];      // query src features
__device__ __align__(16) __half g_Wqt[2 * MDIM * DF];          // Wq[0:128] transposed
__device__ __align__(16) float  g_Q[(size_t)QROWS * MDIM];     // projected queries
__device__ float g_qconst[2][384];
__device__ float g_WoM1[2][384 * 128];
__device__ float g_h1[R2 * DF];
__device__ float g_h2[256 * DF];
__device__ int g_cnt[4];         // [layer][et] partition counters (zeroed by final)
__device__ int g_meta[2];        // tiles0 per layer
__device__ int g_perm1[R1];
__device__ int g_perm2[R2];

// ---------------- helpers ----------------
__device__ __forceinline__ uint32_t smem_u32(const void* p) {
    return (uint32_t)__cvta_generic_to_shared((void*)p);
}
#define CP_ASYNC16(dst, src) \
    asm volatile("cp.async.cg.shared.global [%0], [%1], 16;" :: "r"(dst), "l"(src) : "memory")
#define CP_COMMIT() asm volatile("cp.async.commit_group;" ::: "memory")
#define CP_WAIT(n)  asm volatile("cp.async.wait_group %0;" :: "n"(n) : "memory")
#define LDSM_X4(d0, d1, d2, d3, addr) \
    asm volatile("ldmatrix.sync.aligned.m8n8.x4.shared.b16 {%0,%1,%2,%3}, [%4];" \
        : "=r"(d0), "=r"(d1), "=r"(d2), "=r"(d3) : "r"(addr))

__device__ __forceinline__ void mma16816(float* c, uint32_t a0, uint32_t a1,
                                         uint32_t a2, uint32_t a3,
                                         uint32_t b0, uint32_t b1) {
    asm volatile(
        "mma.sync.aligned.m16n8k16.row.col.f32.f16.f16.f32 "
        "{%0,%1,%2,%3}, {%4,%5,%6,%7}, {%8,%9}, {%0,%1,%2,%3};"
        : "+f"(c[0]), "+f"(c[1]), "+f"(c[2]), "+f"(c[3])
        : "r"(a0), "r"(a1), "r"(a2), "r"(a3), "r"(b0), "r"(b1));
}

// FMA-pipe cos: quadrant range reduction + polys on [-pi/4, pi/4].
__device__ __forceinline__ float fcospoly(float x) {
    float n = rintf(x * 0.6366197723675814f);          // x * 2/pi
    float r = fmaf(n, -1.5707963705062866e0f, x);      // hi of pi/2
    r = fmaf(n, 4.3711388286737929e-8f, r);            // lo correction
    int q = ((int)n) & 3;
    float r2 = r * r;
    float pc = fmaf(r2, fmaf(r2, fmaf(r2, -1.388888889e-3f, 4.166666667e-2f), -0.5f), 1.0f);
    float ps = r * fmaf(r2, fmaf(r2, fmaf(r2, -1.984126984e-4f, 8.333333333e-3f), -1.666666667e-1f), 1.0f);
    float v = (q & 1) ? ps : pc;
    return ((q + 1) & 2) ? -v : v;
}

// ---------------- partition: rank rows by etype (warp-aggregated atomics) ----
__global__ void partA_kernel(const int* __restrict__ et_arr, int* __restrict__ rank,
                             int cb) {
    int r = blockIdx.x * 256 + threadIdx.x;
    int et = (et_arr[r] != 0) ? 1 : 0;
    const unsigned m = 0xFFFFFFFFu;
    unsigned b1 = __ballot_sync(m, et == 1);
    unsigned b0 = ~b1;
    int lane = threadIdx.x & 31;
    unsigned lower = (1u << lane) - 1u;
    int base0 = 0, base1 = 0;
    int l0 = __ffs(b0) - 1, l1 = __ffs(b1) - 1;
    if (b0 && lane == l0) base0 = atomicAdd(&g_cnt[cb + 0], __popc(b0));
    if (b1 && lane == l1) base1 = atomicAdd(&g_cnt[cb + 1], __popc(b1));
    if (b0) base0 = __shfl_sync(m, base0, l0);
    if (b1) base1 = __shfl_sync(m, base1, l1);
    rank[r] = et ? (base1 + __popc(b1 & lower)) : (base0 + __popc(b0 & lower));
}
__global__ void partB_kernel(const int* __restrict__ et_arr, int* __restrict__ perm,
                             int cb, int layer) {
    int r = blockIdx.x * 256 + threadIdx.x;
    int c0 = g_cnt[cb + 0];
    int tiles0 = (c0 + 127) >> 7;
    int et = (et_arr[r] != 0) ? 1 : 0;
    int rk = perm[r];                  // in-place: rank -> position
    perm[r] = et ? (tiles0 * 128 + rk) : rk;
    if (r == 0) g_meta[layer] = tiles0;
}

// ------------- precompute: all weight transforms in one kernel ---------------
__global__ void pre_all(const float* __restrict__ Wrel,
                        const float* __restrict__ Wk,
                        const float* __restrict__ Wv,
                        const float* __restrict__ Wq,
                        const float* __restrict__ Wo,
                        const float* __restrict__ Wm1,
                        const float* __restrict__ phase) {
    int b = blockIdx.x;
    int tid = threadIdx.x;             // 384
    if (b < 3072) {
        if (tid < 128) {
            int l = b / (2 * NOUT);
            int rem = b % (2 * NOUT);
            int et = rem / NOUT;
            int n = rem % NOUT;
            const float* Ws = ((n < MDIM) ? Wk : Wv) + (size_t)l * MDIM * MDIM;
            int nc = (n < MDIM) ? n : n - MDIM;
            const float* wr = Wrel + ((size_t)(l * 2 + et) * DF + tid) * DF;
            float v = 0.f;
            for (int j = 0; j < DF; j++)
                v = fmaf(wr[j], Ws[(size_t)j * MDIM + nc], v);
            size_t base = ((size_t)((l * 2 + et) * NOUT) + n) * KX2;
            g_Wt[base + tid]        = __float2half_rn(v);
            g_Wt[base + 128 + tid]  = __float2half_rn(Ws[(size_t)(DF + tid) * MDIM + nc]);
            g_Wt[base + 256 + tid]  = __float2half_rn(Ws[(size_t)(256 + tid) * MDIM + nc]);
        }
    } else if (b < 3842) {
        int bid = b - 3072;            // 770 = 2*(384+1)
        int l = bid / 385;
        int r = bid % 385;
        if (r == 384) {
            float acc = 0.f;
            for (int j = 0; j < 128; j++)
                acc = fmaf(cosf(phase[j]), Wq[(size_t)l * MDIM * MDIM + (256 + j) * MDIM + tid], acc);
            g_qconst[l][tid] = acc;
        } else if (tid < 128) {
            float acc = 0.f;
            for (int j = 0; j < MDIM; j++)
                acc = fmaf(Wo[(size_t)l * MDIM * MDIM + r * MDIM + j],
                           Wm1[(size_t)(l * 512 + j) * 128 + tid], acc);
            g_WoM1[l][r * 128 + tid] = acc;
        }
    } else {
        int idx = b - 3842;            // 768 = 2*384
        int l = idx / MDIM;
        int n = idx % MDIM;
        if (tid < 128)
            g_Wqt[(size_t)(l * MDIM + n) * DF + tid] =
                __float2half_rn(Wq[(size_t)l * MDIM * MDIM + (size_t)tid * MDIM + n]);
    }
}

// ---------------- qgather: query src features (fp16) ----------------
__global__ void qgather_kernel(int layer, const int* __restrict__ srcA,
                               const int* __restrict__ srcB,
                               const float* __restrict__ n_feat,
                               const float* __restrict__ mem_tab) {
    int n = blockIdx.x * 8 + (threadIdx.x >> 5);
    int u = threadIdx.x & 31;
    int sid = (layer == 0) ? srcA[n] : ((n < BB) ? srcA[n] : srcB[n - BB]);
    int j = 4 * u;
    float4 a = *(const float4*)(n_feat + (size_t)sid * DF + j);
    float4 bb = *(const float4*)(mem_tab + (size_t)sid * DF + j);
    int qrow = ((layer == 0) ? 0 : R2) + n;
    __half2* dst = (__half2*)(g_Xq + (size_t)qrow * DF);
    dst[2 * u]     = __floats2half2_rn(a.x + bb.x, a.y + bb.y);
    dst[2 * u + 1] = __floats2half2_rn(a.z + bb.z, a.w + bb.w);
}

// ---------------- gather: packed X rows (fp16, 4 cols/thread) ----------------
__global__ void gather_kernel(int layer, const int* __restrict__ nghNode,
                              const int* __restrict__ nghEidx,
                              const float* __restrict__ nghT,
                              const int* __restrict__ perm,
                              const float* __restrict__ parentT,
                              const float* __restrict__ n_feat,
                              const float* __restrict__ mem_tab,
                              const float* __restrict__ e_feat,
                              const float* __restrict__ freq,
                              const float* __restrict__ phase) {
    int r = blockIdx.x * 8 + (threadIdx.x >> 5);
    int u = threadIdx.x & 31;
    int node = nghNode[r];
    int eidx = nghEidx[r];
    int pos = perm[r];
    int p = r / KNB;
    float tq = (layer == 0) ? parentT[p] : parentT[p & (BB - 1)];
    float dt = tq - nghT[r];
    int j = 4 * u;
    float4 nf4;
    if (layer == 0) {
        float4 a = *(const float4*)(n_feat + (size_t)node * DF + j);
        float4 b = *(const float4*)(mem_tab + (size_t)node * DF + j);
        nf4 = make_float4(a.x + b.x, a.y + b.y, a.z + b.z, a.w + b.w);
    } else {
        nf4 = *(const float4*)(g_h1 + (size_t)r * DF + j);
    }
    float4 ef4 = *(const float4*)(e_feat + (size_t)eidx * DF + j);
    float4 fr4 = *(const float4*)(freq + j);
    float4 ph4 = *(const float4*)(phase + j);
    float t0 = fcospoly(fmaf(dt, fr4.x, ph4.x));
    float t1 = fcospoly(fmaf(dt, fr4.y, ph4.y));
    float t2 = fcospoly(fmaf(dt, fr4.z, ph4.z));
    float t3 = fcospoly(fmaf(dt, fr4.w, ph4.w));
    __half2* dst = (__half2*)(g_X + (size_t)pos * KX2);
    dst[2 * u]           = __floats2half2_rn(nf4.x, nf4.y);
    dst[2 * u + 1]       = __floats2half2_rn(nf4.z, nf4.w);
    dst[64 + 2 * u]      = __floats2half2_rn(ef4.x, ef4.y);
    dst[64 + 2 * u + 1]  = __floats2half2_rn(ef4.z, ef4.w);
    dst[128 + 2 * u]     = __floats2half2_rn(t0, t1);
    dst[128 + 2 * u + 1] = __floats2half2_rn(t2, t3);
}

// ---------------- HMMA GEMM: KV = X @ Wt[et]' ----------------
#define STR 72                         // padded smem stride in halves (144B rows)
#define ABYTES (128 * STR * 2)         // 18432
#define BUFB   (2 * ABYTES)            // 36864 per stage (A + B)
#define NCHK   (KX2 / 64)              // 6
__global__ __launch_bounds__(256, 2)
void gemm_kernel(int layer) {
    extern __shared__ char smem[];
    const uint32_t smem_base = smem_u32(smem);
    const int tid = threadIdx.x;
    const int wid = tid >> 5;
    const int lane = tid & 31;
    const int n0 = blockIdx.x * 128;
    const int m0 = blockIdx.y * 128;
    const int mbase = (wid >> 1) * 32;
    const int nbase = (wid & 1) * 64;

    const int lrow = lane & 15;
    const int akh  = (lane >> 4) * 8;
    const int brow = (lane & 7) + ((lane >> 4) * 8);
    const int bkh  = ((lane >> 3) & 1) * 8;

    const int tiles0 = g_meta[layer];
    const int et = ((int)blockIdx.y >= tiles0) ? 1 : 0;
    const __half* gW = g_Wt + (size_t)((layer * 2 + et) * NOUT) * KX2;

    float acc[2][8][4];
#pragma unroll
    for (int mt = 0; mt < 2; mt++)
#pragma unroll
        for (int nt = 0; nt < 8; nt++)
#pragma unroll
            for (int q = 0; q < 4; q++) acc[mt][nt][q] = 0.f;

    auto stage = [&](int c) {
        const int kb = c * 64;
        const uint32_t sbase = smem_base + (c % 3) * BUFB;
#pragma unroll
        for (int it = 0; it < 8; it++) {
            int i = tid + it * 256;
            int isB = i >> 10;
            int j = i & 1023;
            int row = j >> 3, seg = j & 7;
            uint32_t dst = sbase + isB * ABYTES + (uint32_t)(row * STR + seg * 8) * 2;
            const __half* src = isB ? (gW + (size_t)(n0 + row) * KX2 + kb + seg * 8)
                                    : (g_X + (size_t)(m0 + row) * KX2 + kb + seg * 8);
            CP_ASYNC16(dst, src);
        }
        CP_COMMIT();
    };

    stage(0);
    stage(1);
    for (int c = 0; c < NCHK; c++) {
        if (c < NCHK - 1) CP_WAIT(1); else CP_WAIT(0);
        __syncthreads();
        const uint32_t sA = smem_base + (c % 3) * BUFB;
        const uint32_t sB = sA + ABYTES;
#pragma unroll
        for (int ks = 0; ks < 4; ks++) {
            const int k16 = ks * 16;
            uint32_t bf[8][2];
#pragma unroll
            for (int nt2 = 0; nt2 < 4; nt2++) {
                uint32_t d0, d1, d2, d3;
                uint32_t addr = sB + (uint32_t)((nbase + nt2 * 16 + brow) * STR + k16 + bkh) * 2;
                LDSM_X4(d0, d1, d2, d3, addr);
                bf[nt2 * 2][0] = d0; bf[nt2 * 2][1] = d1;
                bf[nt2 * 2 + 1][0] = d2; bf[nt2 * 2 + 1][1] = d3;
            }
#pragma unroll
            for (int mt = 0; mt < 2; mt++) {
                uint32_t a0, a1, a2, a3;
                uint32_t addr = sA + (uint32_t)((mbase + mt * 16 + lrow) * STR + k16 + akh) * 2;
                LDSM_X4(a0, a1, a2, a3, addr);
#pragma unroll
                for (int nt = 0; nt < 8; nt++)
                    mma16816(acc[mt][nt], a0, a1, a2, a3, bf[nt][0], bf[nt][1]);
            }
        }
        if (c + 2 < NCHK) stage(c + 2);
    }

#pragma unroll
    for (int mt = 0; mt < 2; mt++) {
#pragma unroll
        for (int nt = 0; nt < 8; nt++) {
            int r = m0 + mbase + mt * 16 + (lane >> 2);
            int ccol = n0 + nbase + nt * 8 + (lane & 3) * 2;
            *(__half2*)(g_KV + (size_t)r * NOUT + ccol) =
                __floats2half2_rn(acc[mt][nt][0], acc[mt][nt][1]);
            *(__half2*)(g_KV + (size_t)(r + 8) * NOUT + ccol) =
                __floats2half2_rn(acc[mt][nt][2], acc[mt][nt][3]);
        }
    }
}

// ---------------- HMMA Q-GEMM: Q = Xq @ Wqt' + qconst ----------------
__global__ __launch_bounds__(256, 2)
void qgemm_kernel(int layer, int qbase) {
    extern __shared__ char smem[];
    const uint32_t smem_base = smem_u32(smem);
    const int tid = threadIdx.x;
    const int wid = tid >> 5;
    const int lane = tid & 31;
    const int n0 = blockIdx.x * 128;
    const int m0 = blockIdx.y * 128;
    const int mbase = (wid >> 1) * 32;
    const int nbase = (wid & 1) * 64;

    const int lrow = lane & 15;
    const int akh  = (lane >> 4) * 8;
    const int brow = (lane & 7) + ((lane >> 4) * 8);
    const int bkh  = ((lane >> 3) & 1) * 8;

    const __half* gW = g_Wqt + (size_t)layer * MDIM * DF;

    float acc[2][8][4];
#pragma unroll
    for (int mt = 0; mt < 2; mt++)
#pragma unroll
        for (int nt = 0; nt < 8; nt++)
#pragma unroll
            for (int q = 0; q < 4; q++) acc[mt][nt][q] = 0.f;

    auto stage = [&](int c) {
        const int kb = c * 64;
        const uint32_t sbase = smem_base + c * BUFB;
#pragma unroll
        for (int it = 0; it < 8; it++) {
            int i = tid + it * 256;
            int isB = i >> 10;
            int j = i & 1023;
            int row = j >> 3, seg = j & 7;
            uint32_t dst = sbase + isB * ABYTES + (uint32_t)(row * STR + seg * 8) * 2;
            const __half* src = isB ? (gW + (size_t)(n0 + row) * DF + kb + seg * 8)
                                    : (g_Xq + (size_t)(qbase + m0 + row) * DF + kb + seg * 8);
            CP_ASYNC16(dst, src);
        }
        CP_COMMIT();
    };

    stage(0);
    stage(1);
    for (int c = 0; c < 2; c++) {
        if (c == 0) CP_WAIT(1); else CP_WAIT(0);
        __syncthreads();
        const uint32_t sA = smem_base + c * BUFB;
        const uint32_t sB = sA + ABYTES;
#pragma unroll
        for (int ks = 0; ks < 4; ks++) {
            const int k16 = ks * 16;
            uint32_t bf[8][2];
#pragma unroll
            for (int nt2 = 0; nt2 < 4; nt2++) {
                uint32_t d0, d1, d2, d3;
                uint32_t addr = sB + (uint32_t)((nbase + nt2 * 16 + brow) * STR + k16 + bkh) * 2;
                LDSM_X4(d0, d1, d2, d3, addr);
                bf[nt2 * 2][0] = d0; bf[nt2 * 2][1] = d1;
                bf[nt2 * 2 + 1][0] = d2; bf[nt2 * 2 + 1][1] = d3;
            }
#pragma unroll
            for (int mt = 0; mt < 2; mt++) {
                uint32_t a0, a1, a2, a3;
                uint32_t addr = sA + (uint32_t)((mbase + mt * 16 + lrow) * STR + k16 + akh) * 2;
                LDSM_X4(a0, a1, a2, a3, addr);
#pragma unroll
                for (int nt = 0; nt < 8; nt++)
                    mma16816(acc[mt][nt], a0, a1, a2, a3, bf[nt][0], bf[nt][1]);
            }
        }
        __syncthreads();
    }

#pragma unroll
    for (int mt = 0; mt < 2; mt++) {
#pragma unroll
        for (int nt = 0; nt < 8; nt++) {
            int r = m0 + mbase + mt * 16 + (lane >> 2);
            int ccol = n0 + nbase + nt * 8 + (lane & 3) * 2;
            float q0 = g_qconst[layer][ccol];
            float q1 = g_qconst[layer][ccol + 1];
            *(float2*)(g_Q + (size_t)(qbase + r) * MDIM + ccol) =
                make_float2(acc[mt][nt][0] + q0, acc[mt][nt][1] + q1);
            *(float2*)(g_Q + (size_t)(qbase + r + 8) * MDIM + ccol) =
                make_float2(acc[mt][nt][2] + q0, acc[mt][nt][3] + q1);
        }
    }
}

// ---------------- attention + MLP: 8 query nodes per CTA ----------------
__global__ __launch_bounds__(256, 1)
void attn_kernel(int layer, int qbase, const int* __restrict__ nghNode,
                 const int* __restrict__ perm,
                 const int* __restrict__ srcA, const int* __restrict__ srcB,
                 const float* __restrict__ n_feat, const float* __restrict__ mem_tab,
                 const float* __restrict__ Wm1, const float* __restrict__ bm1,
                 const float* __restrict__ Wm2, const float* __restrict__ bm2) {
    extern __shared__ float sm[];
    __half* sKVh = (__half*)sm;              // 2 x 31040 halves = 31040 floats
    float* sSRC  = sm + 31040;               // 8*128
    float* sQ    = sm + 32064;               // 8*384
    float* sO    = sm + 35136;               // 8*384
    float* sS    = sm + 38208;               // 160
    float* sA1   = sm + 38368;               // 8*128
    int*   sMask = (int*)(sm + 39392);       // 40  (end 39432 floats)
    const int tid = threadIdx.x;
    const int nb = blockIdx.x;
    const uint32_t smem_base = smem_u32(sm);

    for (int i = tid; i < NPB * DF; i += 256) {
        int node = i >> 7, j = i & 127;
        int n = nb * NPB + node;
        int sid = (layer == 0) ? srcA[n] : ((n < BB) ? srcA[n] : srcB[n - BB]);
        sSRC[i] = n_feat[(size_t)sid * DF + j] + mem_tab[(size_t)sid * DF + j];
    }
    // load precomputed Q (contiguous rows)
    {
        const float4* qsrc = (const float4*)(g_Q + (size_t)(qbase + nb * NPB) * MDIM);
        for (int v = tid; v < NPB * MDIM / 4; v += 256)
            ((float4*)sQ)[v] = qsrc[v];
    }

    auto stageKV = [&](int i, int buf) {
        const int nKNB = (nb * NPB + i) * KNB;
        const uint32_t dbase = smem_base + buf * (KVBUFH * 2);
        for (int v = tid; v < KNB * 96; v += 256) {
            int row = v / 96, c8 = v % 96;
            const __half* src = g_KV + (size_t)perm[nKNB + row] * NOUT + c8 * 8;
            CP_ASYNC16(dbase + (uint32_t)(row * KV2 + c8 * 8) * 2, src);
        }
        CP_COMMIT();
    };
    stageKV(0, 0);
    __syncthreads();

    for (int i = 0; i < NPB; i++) {
        const int n = nb * NPB + i;
        if (i < 7) stageKV(i + 1, (i + 1) & 1);
        if (tid < KNB) sMask[tid] = (nghNode[n * KNB + tid] == 0) ? 1 : 0;
        if (i < 7) CP_WAIT(1); else CP_WAIT(0);
        __syncthreads();
        const __half* kvb = sKVh + (i & 1) * KVBUFH;
        if (tid < HH * KNB) {
            int h = tid / KNB, row = tid % KNB;
            const __half2* kr2 = (const __half2*)(kvb + row * KV2 + h * DHD);
            const float* qk = sQ + i * MDIM + h * DHD;
            float s = 0.f;
#pragma unroll
            for (int d2 = 0; d2 < DHD / 2; d2++) {
                float2 kf = __half22float2(kr2[d2]);
                s = fmaf(qk[2 * d2], kf.x, s);
                s = fmaf(qk[2 * d2 + 1], kf.y, s);
            }
            s *= 0.10206207261596577f;   // 1/sqrt(96)
            if (sMask[row]) s = -1000000000.0f;
            sS[h * KNB + row] = s;
        }
        __syncthreads();
        if (tid < 128) {
            int h = tid >> 5, lane = tid & 31;
            float v0 = sS[h * KNB + lane];
            float v1 = (lane < 8) ? sS[h * KNB + 32 + lane] : -INFINITY;
            float mx = fmaxf(v0, v1);
#pragma unroll
            for (int o = 16; o > 0; o >>= 1)
                mx = fmaxf(mx, __shfl_xor_sync(0xFFFFFFFF, mx, o));
            float e0 = expf(v0 - mx);
            float e1 = (lane < 8) ? expf(v1 - mx) : 0.f;
            float sum = e0 + e1;
#pragma unroll
            for (int o = 16; o > 0; o >>= 1)
                sum += __shfl_xor_sync(0xFFFFFFFF, sum, o);
            float inv = 1.f / sum;
            sS[h * KNB + lane] = e0 * inv;
            if (lane < 8) sS[h * KNB + 32 + lane] = e1 * inv;
        }
        __syncthreads();
        for (int cc = tid; cc < MDIM; cc += 256) {
            int h = cc / DHD;
            const float* a = sS + h * KNB;
            float o = 0.f;
            for (int k = 0; k < KNB; k++)
                o = fmaf(a[k], __half2float(kvb[k * KV2 + MDIM + cc]), o);
            sO[i * MDIM + cc] = o;
        }
        __syncthreads();
    }

    // MLP layer 1 (Wo folded into WoM1): 2 thread-halves x 4 nodes each
    {
        const int half = tid >> 7, col = tid & 127;
        float a[4];
#pragma unroll
        for (int i = 0; i < 4; i++) a[i] = bm1[layer * DF + col];
        const float* w1 = &g_WoM1[layer][col];
        for (int m = 0; m < MDIM; m++) {
            float w = w1[m * DF];
#pragma unroll
            for (int i = 0; i < 4; i++)
                a[i] = fmaf(sO[(half * 4 + i) * MDIM + m], w, a[i]);
        }
        const float* w1b = Wm1 + (size_t)(layer * 512 + MDIM) * DF + col;
        for (int m = 0; m < DF; m++) {
            float w = w1b[m * DF];
#pragma unroll
            for (int i = 0; i < 4; i++)
                a[i] = fmaf(sSRC[(half * 4 + i) * DF + m], w, a[i]);
        }
#pragma unroll
        for (int i = 0; i < 4; i++) sA1[(half * 4 + i) * DF + col] = fmaxf(a[i], 0.f);
    }
    __syncthreads();
    {
        const int half = tid >> 7, col = tid & 127;
        float a[4];
#pragma unroll
        for (int i = 0; i < 4; i++) a[i] = bm2[layer * DF + col];
        const float* w2 = Wm2 + (size_t)layer * DF * DF + col;
        for (int d = 0; d < DF; d++) {
            float w = w2[d * DF];
#pragma unroll
            for (int i = 0; i < 4; i++)
                a[i] = fmaf(sA1[(half * 4 + i) * DF + d], w, a[i]);
        }
        float* hout = (layer == 0) ? g_h1 : g_h2;
#pragma unroll
        for (int i = 0; i < 4; i++)
            hout[(size_t)(nb * NPB + half * 4 + i) * DF + col] = a[i];
    }
}

// ---------------- final bilinear score + sigmoid (+ counter reset) ----------
__global__ void final_kernel(const int* __restrict__ etype_l,
                             const float* __restrict__ Wmatch,
                             const float* __restrict__ bmatch,
                             float* __restrict__ out) {
    __shared__ float ste[128];
    __shared__ float red[128];
    int b = blockIdx.x, d = threadIdx.x;
    if (b == 0 && d < 4) g_cnt[d] = 0;   // reset partition counters for next replay
    int et = etype_l[b];
    ste[d] = g_h2[(BB + b) * DF + d];
    __syncthreads();
    float se = g_h2[b * DF + d];
    const float* wm = Wmatch + (size_t)(et * DF + d) * DF;
    float v = 0.f;
    for (int e = 0; e < DF; e++) v = fmaf(wm[e], ste[e], v);
    red[d] = se * v;
    __syncthreads();
    for (int s = 64; s > 0; s >>= 1) {
        if (d < s) red[d] += red[d + s];
        __syncthreads();
    }
    if (d == 0) {
        float score = red[0] + bmatch[et];
        out[b] = 1.f / (1.f + expf(-score));
    }
}

extern "C" void kernel_launch(void* const* d_in, const int* in_sizes, int n_in,
                              void* d_out, int out_size) {
    const int*   src_idx   = (const int*)d_in[0];
    const int*   tgt_idx   = (const int*)d_in[1];
    const float* cut_time  = (const float*)d_in[2];
    const int*   etype_l   = (const int*)d_in[5];
    const int*   ngh_node2 = (const int*)d_in[6];
    const int*   ngh_eidx2 = (const int*)d_in[7];
    const float* ngh_t2    = (const float*)d_in[8];
    const int*   ngh_et2   = (const int*)d_in[9];
    const int*   ngh_node1 = (const int*)d_in[11];
    const int*   ngh_eidx1 = (const int*)d_in[12];
    const float* ngh_t1    = (const float*)d_in[13];
    const int*   ngh_et1   = (const int*)d_in[14];
    const float* n_feat    = (const float*)d_in[16];
    const float* e_feat    = (const float*)d_in[17];
    const float* mem_tab   = (const float*)d_in[18];
    const float* freq      = (const float*)d_in[19];
    const float* phase     = (const float*)d_in[20];
    const float* Wq        = (const float*)d_in[21];
    const float* Wk        = (const float*)d_in[22];
    const float* Wv        = (const float*)d_in[23];
    const float* Wo        = (const float*)d_in[24];
    const float* Wm1       = (const float*)d_in[25];
    const float* bm1       = (const float*)d_in[26];
    const float* Wm2       = (const float*)d_in[27];
    const float* bm2       = (const float*)d_in[28];
    const float* Wrel      = (const float*)d_in[29];
    const float* Wmatch    = (const float*)d_in[30];
    const float* bmatch    = (const float*)d_in[31];
    float* out = (float*)d_out;

    int* d_perm1; cudaGetSymbolAddress((void**)&d_perm1, g_perm1);
    int* d_perm2; cudaGetSymbolAddress((void**)&d_perm2, g_perm2);

    const int GEMM_SMEM = 3 * BUFB;              // 110592 B
    const int QGEMM_SMEM = 2 * BUFB;             // 73728 B
    const int ATTN_SMEM = 39432 * 4;             // 157728 B
    cudaFuncSetAttribute(gemm_kernel, cudaFuncAttributeMaxDynamicSharedMemorySize, GEMM_SMEM);
    cudaFuncSetAttribute(qgemm_kernel, cudaFuncAttributeMaxDynamicSharedMemorySize, QGEMM_SMEM);
    cudaFuncSetAttribute(attn_kernel, cudaFuncAttributeMaxDynamicSharedMemorySize, ATTN_SMEM);

    // ---- layer 0 ----  (launch #6 = gemm0, the ncu capture target)
    partA_kernel<<<R1 / 256, 256>>>(ngh_et1, d_perm1, 0);                       // 1
    partB_kernel<<<R1 / 256, 256>>>(ngh_et1, d_perm1, 0, 0);                    // 2
    pre_all<<<4610, 384>>>(Wrel, Wk, Wv, Wq, Wo, Wm1, phase);                   // 3
    qgather_kernel<<<R2 / 8, 256>>>(0, ngh_node2, (const int*)0, n_feat, mem_tab); // 4
    gather_kernel<<<R1 / 8, 256>>>(0, ngh_node1, ngh_eidx1, ngh_t1, d_perm1,
                                   ngh_t2, n_feat, mem_tab, e_feat, freq, phase);  // 5
    gemm_kernel<<<dim3(NOUT / 128, R1 / 128 + 1), 256, GEMM_SMEM>>>(0);         // 6
    qgemm_kernel<<<dim3(MDIM / 128, R2 / 128), 256, QGEMM_SMEM>>>(0, 0);        // 7
    attn_kernel<<<R2 / NPB, 256, ATTN_SMEM>>>(0, 0, ngh_node1, d_perm1,
                                              ngh_node2, (const int*)0,
                                              n_feat, mem_tab, Wm1, bm1, Wm2, bm2); // 8

    // ---- layer 1 ----
    partA_kernel<<<R2 / 256, 256>>>(ngh_et2, d_perm2, 2);
    partB_kernel<<<R2 / 256, 256>>>(ngh_et2, d_perm2, 2, 1);
    qgather_kernel<<<256 / 8, 256>>>(1, src_idx, tgt_idx, n_feat, mem_tab);
    gather_kernel<<<R2 / 8, 256>>>(1, ngh_node2, ngh_eidx2, ngh_t2, d_perm2,
                                   cut_time, n_feat, mem_tab, e_feat, freq, phase);
    gemm_kernel<<<dim3(NOUT / 128, R2 / 128 + 1), 256, GEMM_SMEM>>>(1);
    qgemm_kernel<<<dim3(MDIM / 128, 256 / 128), 256, QGEMM_SMEM>>>(1, R2);
    attn_kernel<<<256 / NPB, 256, ATTN_SMEM>>>(1, R2, ngh_node2, d_perm2,
                                               src_idx, tgt_idx,
                                               n_feat, mem_tab, Wm1, bm1, Wm2, bm2);

    final_kernel<<<BB, 128>>>(etype_l, Wmatch, bmatch, out);
}

// round 16
// speedup vs baseline: 1.8706x; 1.0728x over previous
#include <cuda_runtime.h>
#include <cuda_fp16.h>
#include <math.h>
#include <stdint.h>

#define KNB 40
#define DF 128
#define MDIM 384
#define HH 4
#define DHD 96
#define BB 128
#define R1 409600
#define R2 10240
#define KX2 384              // packed K: [nf | ef | tf]
#define NOUT 768
#define NPB 8
#define KSTR 392             // padded halves per K/V half-row (784 B = 16-aligned)
#define SLOTH (KNB * KSTR)   // 15680 halves per ring slot
#define QROWS (R2 + 256)     // 10496 query rows total (layer0 + layer1)

// ---------------- scratch (__device__ globals, no allocation) ----------------
__device__ __align__(16) __half g_X[(size_t)(R1 + 128) * KX2];
__device__ __align__(16) __half g_Wt[2 * 2 * NOUT * KX2];      // [l][et][n][k]
__device__ __align__(16) __half g_KV[(size_t)(R1 + 128) * NOUT];
__device__ __align__(16) __half g_Xq[(size_t)QROWS * DF];      // query src features
__device__ __align__(16) __half g_Wqt[2 * MDIM * DF];          // Wq[0:128] transposed
__device__ __align__(16) float  g_Q[(size_t)QROWS * MDIM];     // projected queries
__device__ float g_qconst[2][384];
__device__ float g_WoM1[2][384 * 128];
__device__ float g_h1[R2 * DF];
__device__ float g_h2[256 * DF];
__device__ int g_cnt[4];         // [layer][et] partition counters (zeroed by final)
__device__ int g_meta[2];        // tiles0 per layer
__device__ int g_perm1[R1];
__device__ int g_perm2[R2];

// ---------------- helpers ----------------
__device__ __forceinline__ uint32_t smem_u32(const void* p) {
    return (uint32_t)__cvta_generic_to_shared((void*)p);
}
#define CP_ASYNC16(dst, src) \
    asm volatile("cp.async.cg.shared.global [%0], [%1], 16;" :: "r"(dst), "l"(src) : "memory")
#define CP_COMMIT() asm volatile("cp.async.commit_group;" ::: "memory")
#define CP_WAIT(n)  asm volatile("cp.async.wait_group %0;" :: "n"(n) : "memory")
#define LDSM_X4(d0, d1, d2, d3, addr) \
    asm volatile("ldmatrix.sync.aligned.m8n8.x4.shared.b16 {%0,%1,%2,%3}, [%4];" \
        : "=r"(d0), "=r"(d1), "=r"(d2), "=r"(d3) : "r"(addr))

__device__ __forceinline__ void mma16816(float* c, uint32_t a0, uint32_t a1,
                                         uint32_t a2, uint32_t a3,
                                         uint32_t b0, uint32_t b1) {
    asm volatile(
        "mma.sync.aligned.m16n8k16.row.col.f32.f16.f16.f32 "
        "{%0,%1,%2,%3}, {%4,%5,%6,%7}, {%8,%9}, {%0,%1,%2,%3};"
        : "+f"(c[0]), "+f"(c[1]), "+f"(c[2]), "+f"(c[3])
        : "r"(a0), "r"(a1), "r"(a2), "r"(a3), "r"(b0), "r"(b1));
}

// FMA-pipe cos: quadrant range reduction + polys on [-pi/4, pi/4].
__device__ __forceinline__ float fcospoly(float x) {
    float n = rintf(x * 0.6366197723675814f);          // x * 2/pi
    float r = fmaf(n, -1.5707963705062866e0f, x);      // hi of pi/2
    r = fmaf(n, 4.3711388286737929e-8f, r);            // lo correction
    int q = ((int)n) & 3;
    float r2 = r * r;
    float pc = fmaf(r2, fmaf(r2, fmaf(r2, -1.388888889e-3f, 4.166666667e-2f), -0.5f), 1.0f);
    float ps = r * fmaf(r2, fmaf(r2, fmaf(r2, -1.984126984e-4f, 8.333333333e-3f), -1.666666667e-1f), 1.0f);
    float v = (q & 1) ? ps : pc;
    return ((q + 1) & 2) ? -v : v;
}

// ---------------- partition: rank rows by etype (warp-aggregated atomics) ----
__global__ void partA_kernel(const int* __restrict__ et_arr, int* __restrict__ rank,
                             int cb) {
    int r = blockIdx.x * 256 + threadIdx.x;
    int et = (et_arr[r] != 0) ? 1 : 0;
    const unsigned m = 0xFFFFFFFFu;
    unsigned b1 = __ballot_sync(m, et == 1);
    unsigned b0 = ~b1;
    int lane = threadIdx.x & 31;
    unsigned lower = (1u << lane) - 1u;
    int base0 = 0, base1 = 0;
    int l0 = __ffs(b0) - 1, l1 = __ffs(b1) - 1;
    if (b0 && lane == l0) base0 = atomicAdd(&g_cnt[cb + 0], __popc(b0));
    if (b1 && lane == l1) base1 = atomicAdd(&g_cnt[cb + 1], __popc(b1));
    if (b0) base0 = __shfl_sync(m, base0, l0);
    if (b1) base1 = __shfl_sync(m, base1, l1);
    rank[r] = et ? (base1 + __popc(b1 & lower)) : (base0 + __popc(b0 & lower));
}
__global__ void partB_kernel(const int* __restrict__ et_arr, int* __restrict__ perm,
                             int cb, int layer) {
    int r = blockIdx.x * 256 + threadIdx.x;
    int c0 = g_cnt[cb + 0];
    int tiles0 = (c0 + 127) >> 7;
    int et = (et_arr[r] != 0) ? 1 : 0;
    int rk = perm[r];                  // in-place: rank -> position
    perm[r] = et ? (tiles0 * 128 + rk) : rk;
    if (r == 0) g_meta[layer] = tiles0;
}

// ------------- precompute: all weight transforms in one kernel ---------------
__global__ void pre_all(const float* __restrict__ Wrel,
                        const float* __restrict__ Wk,
                        const float* __restrict__ Wv,
                        const float* __restrict__ Wq,
                        const float* __restrict__ Wo,
                        const float* __restrict__ Wm1,
                        const float* __restrict__ phase) {
    int b = blockIdx.x;
    int tid = threadIdx.x;             // 384
    if (b < 3072) {
        if (tid < 128) {
            int l = b / (2 * NOUT);
            int rem = b % (2 * NOUT);
            int et = rem / NOUT;
            int n = rem % NOUT;
            const float* Ws = ((n < MDIM) ? Wk : Wv) + (size_t)l * MDIM * MDIM;
            int nc = (n < MDIM) ? n : n - MDIM;
            const float* wr = Wrel + ((size_t)(l * 2 + et) * DF + tid) * DF;
            float v = 0.f;
            for (int j = 0; j < DF; j++)
                v = fmaf(wr[j], Ws[(size_t)j * MDIM + nc], v);
            size_t base = ((size_t)((l * 2 + et) * NOUT) + n) * KX2;
            g_Wt[base + tid]        = __float2half_rn(v);
            g_Wt[base + 128 + tid]  = __float2half_rn(Ws[(size_t)(DF + tid) * MDIM + nc]);
            g_Wt[base + 256 + tid]  = __float2half_rn(Ws[(size_t)(256 + tid) * MDIM + nc]);
        }
    } else if (b < 3842) {
        int bid = b - 3072;            // 770 = 2*(384+1)
        int l = bid / 385;
        int r = bid % 385;
        if (r == 384) {
            float acc = 0.f;
            for (int j = 0; j < 128; j++)
                acc = fmaf(cosf(phase[j]), Wq[(size_t)l * MDIM * MDIM + (256 + j) * MDIM + tid], acc);
            g_qconst[l][tid] = acc;
        } else if (tid < 128) {
            float acc = 0.f;
            for (int j = 0; j < MDIM; j++)
                acc = fmaf(Wo[(size_t)l * MDIM * MDIM + r * MDIM + j],
                           Wm1[(size_t)(l * 512 + j) * 128 + tid], acc);
            g_WoM1[l][r * 128 + tid] = acc;
        }
    } else {
        int idx = b - 3842;            // 768 = 2*384
        int l = idx / MDIM;
        int n = idx % MDIM;
        if (tid < 128)
            g_Wqt[(size_t)(l * MDIM + n) * DF + tid] =
                __float2half_rn(Wq[(size_t)l * MDIM * MDIM + (size_t)tid * MDIM + n]);
    }
}

// ---------------- qgather: query src features (fp16) ----------------
__global__ void qgather_kernel(int layer, const int* __restrict__ srcA,
                               const int* __restrict__ srcB,
                               const float* __restrict__ n_feat,
                               const float* __restrict__ mem_tab) {
    int n = blockIdx.x * 8 + (threadIdx.x >> 5);
    int u = threadIdx.x & 31;
    int sid = (layer == 0) ? srcA[n] : ((n < BB) ? srcA[n] : srcB[n - BB]);
    int j = 4 * u;
    float4 a = *(const float4*)(n_feat + (size_t)sid * DF + j);
    float4 bb = *(const float4*)(mem_tab + (size_t)sid * DF + j);
    int qrow = ((layer == 0) ? 0 : R2) + n;
    __half2* dst = (__half2*)(g_Xq + (size_t)qrow * DF);
    dst[2 * u]     = __floats2half2_rn(a.x + bb.x, a.y + bb.y);
    dst[2 * u + 1] = __floats2half2_rn(a.z + bb.z, a.w + bb.w);
}

// ---------------- gather: packed X rows (fp16, 4 cols/thread) ----------------
__global__ void gather_kernel(int layer, const int* __restrict__ nghNode,
                              const int* __restrict__ nghEidx,
                              const float* __restrict__ nghT,
                              const int* __restrict__ perm,
                              const float* __restrict__ parentT,
                              const float* __restrict__ n_feat,
                              const float* __restrict__ mem_tab,
                              const float* __restrict__ e_feat,
                              const float* __restrict__ freq,
                              const float* __restrict__ phase) {
    int r = blockIdx.x * 8 + (threadIdx.x >> 5);
    int u = threadIdx.x & 31;
    int node = nghNode[r];
    int eidx = nghEidx[r];
    int pos = perm[r];
    int p = r / KNB;
    float tq = (layer == 0) ? parentT[p] : parentT[p & (BB - 1)];
    float dt = tq - nghT[r];
    int j = 4 * u;
    float4 nf4;
    if (layer == 0) {
        float4 a = *(const float4*)(n_feat + (size_t)node * DF + j);
        float4 b = *(const float4*)(mem_tab + (size_t)node * DF + j);
        nf4 = make_float4(a.x + b.x, a.y + b.y, a.z + b.z, a.w + b.w);
    } else {
        nf4 = *(const float4*)(g_h1 + (size_t)r * DF + j);
    }
    float4 ef4 = *(const float4*)(e_feat + (size_t)eidx * DF + j);
    float4 fr4 = *(const float4*)(freq + j);
    float4 ph4 = *(const float4*)(phase + j);
    float t0 = fcospoly(fmaf(dt, fr4.x, ph4.x));
    float t1 = fcospoly(fmaf(dt, fr4.y, ph4.y));
    float t2 = fcospoly(fmaf(dt, fr4.z, ph4.z));
    float t3 = fcospoly(fmaf(dt, fr4.w, ph4.w));
    __half2* dst = (__half2*)(g_X + (size_t)pos * KX2);
    dst[2 * u]           = __floats2half2_rn(nf4.x, nf4.y);
    dst[2 * u + 1]       = __floats2half2_rn(nf4.z, nf4.w);
    dst[64 + 2 * u]      = __floats2half2_rn(ef4.x, ef4.y);
    dst[64 + 2 * u + 1]  = __floats2half2_rn(ef4.z, ef4.w);
    dst[128 + 2 * u]     = __floats2half2_rn(t0, t1);
    dst[128 + 2 * u + 1] = __floats2half2_rn(t2, t3);
}

// ---------------- HMMA GEMM: KV = X @ Wt[et]' ----------------
#define STR 72                         // padded smem stride in halves (144B rows)
#define ABYTES (128 * STR * 2)         // 18432
#define BUFB   (2 * ABYTES)            // 36864 per stage (A + B)
#define NCHK   (KX2 / 64)              // 6
__global__ __launch_bounds__(256, 2)
void gemm_kernel(int layer) {
    extern __shared__ char smem[];
    const uint32_t smem_base = smem_u32(smem);
    const int tid = threadIdx.x;
    const int wid = tid >> 5;
    const int lane = tid & 31;
    const int n0 = blockIdx.x * 128;
    const int m0 = blockIdx.y * 128;
    const int mbase = (wid >> 1) * 32;
    const int nbase = (wid & 1) * 64;

    const int lrow = lane & 15;
    const int akh  = (lane >> 4) * 8;
    const int brow = (lane & 7) + ((lane >> 4) * 8);
    const int bkh  = ((lane >> 3) & 1) * 8;

    const int tiles0 = g_meta[layer];
    const int et = ((int)blockIdx.y >= tiles0) ? 1 : 0;
    const __half* gW = g_Wt + (size_t)((layer * 2 + et) * NOUT) * KX2;

    float acc[2][8][4];
#pragma unroll
    for (int mt = 0; mt < 2; mt++)
#pragma unroll
        for (int nt = 0; nt < 8; nt++)
#pragma unroll
            for (int q = 0; q < 4; q++) acc[mt][nt][q] = 0.f;

    auto stage = [&](int c) {
        const int kb = c * 64;
        const uint32_t sbase = smem_base + (c % 3) * BUFB;
#pragma unroll
        for (int it = 0; it < 8; it++) {
            int i = tid + it * 256;
            int isB = i >> 10;
            int j = i & 1023;
            int row = j >> 3, seg = j & 7;
            uint32_t dst = sbase + isB * ABYTES + (uint32_t)(row * STR + seg * 8) * 2;
            const __half* src = isB ? (gW + (size_t)(n0 + row) * KX2 + kb + seg * 8)
                                    : (g_X + (size_t)(m0 + row) * KX2 + kb + seg * 8);
            CP_ASYNC16(dst, src);
        }
        CP_COMMIT();
    };

    stage(0);
    stage(1);
    for (int c = 0; c < NCHK; c++) {
        if (c < NCHK - 1) CP_WAIT(1); else CP_WAIT(0);
        __syncthreads();
        const uint32_t sA = smem_base + (c % 3) * BUFB;
        const uint32_t sB = sA + ABYTES;
#pragma unroll
        for (int ks = 0; ks < 4; ks++) {
            const int k16 = ks * 16;
            uint32_t bf[8][2];
#pragma unroll
            for (int nt2 = 0; nt2 < 4; nt2++) {
                uint32_t d0, d1, d2, d3;
                uint32_t addr = sB + (uint32_t)((nbase + nt2 * 16 + brow) * STR + k16 + bkh) * 2;
                LDSM_X4(d0, d1, d2, d3, addr);
                bf[nt2 * 2][0] = d0; bf[nt2 * 2][1] = d1;
                bf[nt2 * 2 + 1][0] = d2; bf[nt2 * 2 + 1][1] = d3;
            }
#pragma unroll
            for (int mt = 0; mt < 2; mt++) {
                uint32_t a0, a1, a2, a3;
                uint32_t addr = sA + (uint32_t)((mbase + mt * 16 + lrow) * STR + k16 + akh) * 2;
                LDSM_X4(a0, a1, a2, a3, addr);
#pragma unroll
                for (int nt = 0; nt < 8; nt++)
                    mma16816(acc[mt][nt], a0, a1, a2, a3, bf[nt][0], bf[nt][1]);
            }
        }
        if (c + 2 < NCHK) stage(c + 2);
    }

#pragma unroll
    for (int mt = 0; mt < 2; mt++) {
#pragma unroll
        for (int nt = 0; nt < 8; nt++) {
            int r = m0 + mbase + mt * 16 + (lane >> 2);
            int ccol = n0 + nbase + nt * 8 + (lane & 3) * 2;
            *(__half2*)(g_KV + (size_t)r * NOUT + ccol) =
                __floats2half2_rn(acc[mt][nt][0], acc[mt][nt][1]);
            *(__half2*)(g_KV + (size_t)(r + 8) * NOUT + ccol) =
                __floats2half2_rn(acc[mt][nt][2], acc[mt][nt][3]);
        }
    }
}

// ---------------- HMMA Q-GEMM: Q = Xq @ Wqt' + qconst ----------------
__global__ __launch_bounds__(256, 2)
void qgemm_kernel(int layer, int qbase) {
    extern __shared__ char smem[];
    const uint32_t smem_base = smem_u32(smem);
    const int tid = threadIdx.x;
    const int wid = tid >> 5;
    const int lane = tid & 31;
    const int n0 = blockIdx.x * 128;
    const int m0 = blockIdx.y * 128;
    const int mbase = (wid >> 1) * 32;
    const int nbase = (wid & 1) * 64;

    const int lrow = lane & 15;
    const int akh  = (lane >> 4) * 8;
    const int brow = (lane & 7) + ((lane >> 4) * 8);
    const int bkh  = ((lane >> 3) & 1) * 8;

    const __half* gW = g_Wqt + (size_t)layer * MDIM * DF;

    float acc[2][8][4];
#pragma unroll
    for (int mt = 0; mt < 2; mt++)
#pragma unroll
        for (int nt = 0; nt < 8; nt++)
#pragma unroll
            for (int q = 0; q < 4; q++) acc[mt][nt][q] = 0.f;

    auto stage = [&](int c) {
        const int kb = c * 64;
        const uint32_t sbase = smem_base + c * BUFB;
#pragma unroll
        for (int it = 0; it < 8; it++) {
            int i = tid + it * 256;
            int isB = i >> 10;
            int j = i & 1023;
            int row = j >> 3, seg = j & 7;
            uint32_t dst = sbase + isB * ABYTES + (uint32_t)(row * STR + seg * 8) * 2;
            const __half* src = isB ? (gW + (size_t)(n0 + row) * DF + kb + seg * 8)
                                    : (g_Xq + (size_t)(qbase + m0 + row) * DF + kb + seg * 8);
            CP_ASYNC16(dst, src);
        }
        CP_COMMIT();
    };

    stage(0);
    stage(1);
    for (int c = 0; c < 2; c++) {
        if (c == 0) CP_WAIT(1); else CP_WAIT(0);
        __syncthreads();
        const uint32_t sA = smem_base + c * BUFB;
        const uint32_t sB = sA + ABYTES;
#pragma unroll
        for (int ks = 0; ks < 4; ks++) {
            const int k16 = ks * 16;
            uint32_t bf[8][2];
#pragma unroll
            for (int nt2 = 0; nt2 < 4; nt2++) {
                uint32_t d0, d1, d2, d3;
                uint32_t addr = sB + (uint32_t)((nbase + nt2 * 16 + brow) * STR + k16 + bkh) * 2;
                LDSM_X4(d0, d1, d2, d3, addr);
                bf[nt2 * 2][0] = d0; bf[nt2 * 2][1] = d1;
                bf[nt2 * 2 + 1][0] = d2; bf[nt2 * 2 + 1][1] = d3;
            }
#pragma unroll
            for (int mt = 0; mt < 2; mt++) {
                uint32_t a0, a1, a2, a3;
                uint32_t addr = sA + (uint32_t)((mbase + mt * 16 + lrow) * STR + k16 + akh) * 2;
                LDSM_X4(a0, a1, a2, a3, addr);
#pragma unroll
                for (int nt = 0; nt < 8; nt++)
                    mma16816(acc[mt][nt], a0, a1, a2, a3, bf[nt][0], bf[nt][1]);
            }
        }
        __syncthreads();
    }

#pragma unroll
    for (int mt = 0; mt < 2; mt++) {
#pragma unroll
        for (int nt = 0; nt < 8; nt++) {
            int r = m0 + mbase + mt * 16 + (lane >> 2);
            int ccol = n0 + nbase + nt * 8 + (lane & 3) * 2;
            float q0 = g_qconst[layer][ccol];
            float q1 = g_qconst[layer][ccol + 1];
            *(float2*)(g_Q + (size_t)(qbase + r) * MDIM + ccol) =
                make_float2(acc[mt][nt][0] + q0, acc[mt][nt][1] + q1);
            *(float2*)(g_Q + (size_t)(qbase + r + 8) * MDIM + ccol) =
                make_float2(acc[mt][nt][2] + q0, acc[mt][nt][3] + q1);
        }
    }
}

// ---------------- attention + MLP: 8 nodes/CTA, 3-slot K/V ring, 2 CTAs/SM ---
// Ring: K(i) in slot (2i)%3, V(i) in slot (2i+1)%3.
// Prologue stages K0,V0,K1. Per node: wait K -> scores -> stage V(i+1) into
// K(i)'s slot -> softmax -> wait V -> AV -> stage K(i+2) into V(i)'s slot.
__global__ __launch_bounds__(256, 2)
void attn_kernel(int layer, int qbase, const int* __restrict__ nghNode,
                 const int* __restrict__ perm,
                 const float* __restrict__ Wm1, const float* __restrict__ bm1,
                 const float* __restrict__ Wm2, const float* __restrict__ bm2) {
    extern __shared__ float sm[];
    __half* sSlot = (__half*)sm;             // 3*15680 halves = 23520 floats
    __half* sQh   = (__half*)(sm + 23520);   // 8*384 halves  = 1536 floats
    __half* sSRCh = (__half*)(sm + 25056);   // 8*128 halves  = 512 floats
    float*  sS    = sm + 25568;              // 160
    int*    sMask = (int*)(sm + 25728);      // 40
    float*  sO    = sm + 25768;              // 8*384 = 3072 -> ends 28840 (115360 B)
    float*  sA1   = sm;                      // overlay on slots after node loop
    const int tid = threadIdx.x;
    const int nb = blockIdx.x;
    const uint32_t smem_base = smem_u32(sm);

    // Q (fp32 global -> fp16 smem) and src features (fp16, from g_Xq)
    {
        const float4* qsrc = (const float4*)(g_Q + (size_t)(qbase + nb * NPB) * MDIM);
        for (int v = tid; v < NPB * MDIM / 4; v += 256) {
            float4 q4 = qsrc[v];
            ((__half2*)sQh)[2 * v]     = __floats2half2_rn(q4.x, q4.y);
            ((__half2*)sQh)[2 * v + 1] = __floats2half2_rn(q4.z, q4.w);
        }
        const uint4* ssrc = (const uint4*)(g_Xq + (size_t)(qbase + nb * NPB) * DF);
        for (int v = tid; v < NPB * DF / 8; v += 256)
            ((uint4*)sSRCh)[v] = ssrc[v];
    }

    // stage one K/V half of node i into a ring slot (half: 0=K, 1=V)
    auto stageHalf = [&](int i, int slot, int half) {
        const int nKNB = (nb * NPB + i) * KNB;
        const uint32_t dbase = smem_base + (uint32_t)slot * (SLOTH * 2);
        for (int v = tid; v < KNB * 48; v += 256) {
            int row = v / 48, seg = v % 48;
            const __half* src = g_KV + (size_t)perm[nKNB + row] * NOUT + half * MDIM + seg * 8;
            CP_ASYNC16(dbase + (uint32_t)(row * KSTR + seg * 8) * 2, src);
        }
        CP_COMMIT();
    };
    stageHalf(0, 0, 0);        // K0
    stageHalf(0, 1, 1);        // V0
    stageHalf(1, 2, 0);        // K1
    __syncthreads();

    for (int i = 0; i < NPB; i++) {
        const int n = nb * NPB + i;
        const int sK = (2 * i) % 3;
        const int sV = (2 * i + 1) % 3;
        if (tid < KNB) sMask[tid] = (nghNode[n * KNB + tid] == 0) ? 1 : 0;
        if (i < NPB - 1) CP_WAIT(2); else CP_WAIT(1);   // K(i) ready
        __syncthreads();
        const __half* kb = sSlot + sK * SLOTH;
        // scores
        if (tid < HH * KNB) {
            int h = tid / KNB, row = tid % KNB;
            const __half2* kr2 = (const __half2*)(kb + row * KSTR + h * DHD);
            const __half2* qr2 = (const __half2*)(sQh + i * MDIM + h * DHD);
            float s = 0.f;
#pragma unroll
            for (int d2 = 0; d2 < DHD / 2; d2++) {
                float2 kf = __half22float2(kr2[d2]);
                float2 qf = __half22float2(qr2[d2]);
                s = fmaf(qf.x, kf.x, s);
                s = fmaf(qf.y, kf.y, s);
            }
            s *= 0.10206207261596577f;   // 1/sqrt(96)
            if (sMask[row]) s = -1000000000.0f;
            sS[h * KNB + row] = s;
        }
        __syncthreads();                 // K(i) consumed; sS complete
        if (i + 1 < NPB) stageHalf(i + 1, sK, 1);    // V(i+1) into K(i)'s slot
        // warp-parallel softmax (overlaps V staging)
        if (tid < 128) {
            int h = tid >> 5, lane = tid & 31;
            float v0 = sS[h * KNB + lane];
            float v1 = (lane < 8) ? sS[h * KNB + 32 + lane] : -INFINITY;
            float mx = fmaxf(v0, v1);
#pragma unroll
            for (int o = 16; o > 0; o >>= 1)
                mx = fmaxf(mx, __shfl_xor_sync(0xFFFFFFFF, mx, o));
            float e0 = expf(v0 - mx);
            float e1 = (lane < 8) ? expf(v1 - mx) : 0.f;
            float sum = e0 + e1;
#pragma unroll
            for (int o = 16; o > 0; o >>= 1)
                sum += __shfl_xor_sync(0xFFFFFFFF, sum, o);
            float inv = 1.f / sum;
            sS[h * KNB + lane] = e0 * inv;
            if (lane < 8) sS[h * KNB + 32 + lane] = e1 * inv;
        }
        if (i < NPB - 1) CP_WAIT(2); else CP_WAIT(0);   // V(i) ready
        __syncthreads();
        const __half* vb = sSlot + sV * SLOTH;
        // o = a @ V
        for (int cc = tid; cc < MDIM; cc += 256) {
            int h = cc / DHD;
            const float* a = sS + h * KNB;
            float o = 0.f;
            for (int k = 0; k < KNB; k++)
                o = fmaf(a[k], __half2float(vb[k * KSTR + cc]), o);
            sO[i * MDIM + cc] = o;
        }
        __syncthreads();                 // V(i) consumed
        if (i + 2 < NPB) stageHalf(i + 2, sV, 0);    // K(i+2) into V(i)'s slot
    }

    // MLP layer 1 (Wo folded into WoM1): 2 thread-halves x 4 nodes each
    // sA1 overlays dead slot memory (loop-final __syncthreads precedes).
    {
        const int half = tid >> 7, col = tid & 127;
        float a[4];
#pragma unroll
        for (int i = 0; i < 4; i++) a[i] = bm1[layer * DF + col];
        const float* w1 = &g_WoM1[layer][col];
        for (int m = 0; m < MDIM; m++) {
            float w = w1[m * DF];
#pragma unroll
            for (int i = 0; i < 4; i++)
                a[i] = fmaf(sO[(half * 4 + i) * MDIM + m], w, a[i]);
        }
        const float* w1b = Wm1 + (size_t)(layer * 512 + MDIM) * DF + col;
        for (int m = 0; m < DF; m++) {
            float w = w1b[m * DF];
#pragma unroll
            for (int i = 0; i < 4; i++)
                a[i] = fmaf(__half2float(sSRCh[(half * 4 + i) * DF + m]), w, a[i]);
        }
#pragma unroll
        for (int i = 0; i < 4; i++) sA1[(half * 4 + i) * DF + col] = fmaxf(a[i], 0.f);
    }
    __syncthreads();
    {
        const int half = tid >> 7, col = tid & 127;
        float a[4];
#pragma unroll
        for (int i = 0; i < 4; i++) a[i] = bm2[layer * DF + col];
        const float* w2 = Wm2 + (size_t)layer * DF * DF + col;
        for (int d = 0; d < DF; d++) {
            float w = w2[d * DF];
#pragma unroll
            for (int i = 0; i < 4; i++)
                a[i] = fmaf(sA1[(half * 4 + i) * DF + d], w, a[i]);
        }
        float* hout = (layer == 0) ? g_h1 : g_h2;
#pragma unroll
        for (int i = 0; i < 4; i++)
            hout[(size_t)(nb * NPB + half * 4 + i) * DF + col] = a[i];
    }
}

// ---------------- final bilinear score + sigmoid (+ counter reset) ----------
__global__ void final_kernel(const int* __restrict__ etype_l,
                             const float* __restrict__ Wmatch,
                             const float* __restrict__ bmatch,
                             float* __restrict__ out) {
    __shared__ float ste[128];
    __shared__ float red[128];
    int b = blockIdx.x, d = threadIdx.x;
    if (b == 0 && d < 4) g_cnt[d] = 0;   // reset partition counters for next replay
    int et = etype_l[b];
    ste[d] = g_h2[(BB + b) * DF + d];
    __syncthreads();
    float se = g_h2[b * DF + d];
    const float* wm = Wmatch + (size_t)(et * DF + d) * DF;
    float v = 0.f;
    for (int e = 0; e < DF; e++) v = fmaf(wm[e], ste[e], v);
    red[d] = se * v;
    __syncthreads();
    for (int s = 64; s > 0; s >>= 1) {
        if (d < s) red[d] += red[d + s];
        __syncthreads();
    }
    if (d == 0) {
        float score = red[0] + bmatch[et];
        out[b] = 1.f / (1.f + expf(-score));
    }
}

extern "C" void kernel_launch(void* const* d_in, const int* in_sizes, int n_in,
                              void* d_out, int out_size) {
    const int*   src_idx   = (const int*)d_in[0];
    const int*   tgt_idx   = (const int*)d_in[1];
    const float* cut_time  = (const float*)d_in[2];
    const int*   etype_l   = (const int*)d_in[5];
    const int*   ngh_node2 = (const int*)d_in[6];
    const int*   ngh_eidx2 = (const int*)d_in[7];
    const float* ngh_t2    = (const float*)d_in[8];
    const int*   ngh_et2   = (const int*)d_in[9];
    const int*   ngh_node1 = (const int*)d_in[11];
    const int*   ngh_eidx1 = (const int*)d_in[12];
    const float* ngh_t1    = (const float*)d_in[13];
    const int*   ngh_et1   = (const int*)d_in[14];
    const float* n_feat    = (const float*)d_in[16];
    const float* e_feat    = (const float*)d_in[17];
    const float* mem_tab   = (const float*)d_in[18];
    const float* freq      = (const float*)d_in[19];
    const float* phase     = (const float*)d_in[20];
    const float* Wq        = (const float*)d_in[21];
    const float* Wk        = (const float*)d_in[22];
    const float* Wv        = (const float*)d_in[23];
    const float* Wo        = (const float*)d_in[24];
    const float* Wm1       = (const float*)d_in[25];
    const float* bm1       = (const float*)d_in[26];
    const float* Wm2       = (const float*)d_in[27];
    const float* bm2       = (const float*)d_in[28];
    const float* Wrel      = (const float*)d_in[29];
    const float* Wmatch    = (const float*)d_in[30];
    const float* bmatch    = (const float*)d_in[31];
    float* out = (float*)d_out;

    int* d_perm1; cudaGetSymbolAddress((void**)&d_perm1, g_perm1);
    int* d_perm2; cudaGetSymbolAddress((void**)&d_perm2, g_perm2);

    const int GEMM_SMEM = 3 * BUFB;              // 110592 B
    const int QGEMM_SMEM = 2 * BUFB;             // 73728 B
    const int ATTN_SMEM = 28840 * 4;             // 115360 B (2 CTAs/SM)
    cudaFuncSetAttribute(gemm_kernel, cudaFuncAttributeMaxDynamicSharedMemorySize, GEMM_SMEM);
    cudaFuncSetAttribute(qgemm_kernel, cudaFuncAttributeMaxDynamicSharedMemorySize, QGEMM_SMEM);
    cudaFuncSetAttribute(attn_kernel, cudaFuncAttributeMaxDynamicSharedMemorySize, ATTN_SMEM);

    // ---- layer 0 ----
    partA_kernel<<<R1 / 256, 256>>>(ngh_et1, d_perm1, 0);
    partB_kernel<<<R1 / 256, 256>>>(ngh_et1, d_perm1, 0, 0);
    pre_all<<<4610, 384>>>(Wrel, Wk, Wv, Wq, Wo, Wm1, phase);
    qgather_kernel<<<R2 / 8, 256>>>(0, ngh_node2, (const int*)0, n_feat, mem_tab);
    gather_kernel<<<R1 / 8, 256>>>(0, ngh_node1, ngh_eidx1, ngh_t1, d_perm1,
                                   ngh_t2, n_feat, mem_tab, e_feat, freq, phase);
    gemm_kernel<<<dim3(NOUT / 128, R1 / 128 + 1), 256, GEMM_SMEM>>>(0);
    qgemm_kernel<<<dim3(MDIM / 128, R2 / 128), 256, QGEMM_SMEM>>>(0, 0);
    attn_kernel<<<R2 / NPB, 256, ATTN_SMEM>>>(0, 0, ngh_node1, d_perm1,
                                              Wm1, bm1, Wm2, bm2);

    // ---- layer 1 ----
    partA_kernel<<<R2 / 256, 256>>>(ngh_et2, d_perm2, 2);
    partB_kernel<<<R2 / 256, 256>>>(ngh_et2, d_perm2, 2, 1);
    qgather_kernel<<<256 / 8, 256>>>(1, src_idx, tgt_idx, n_feat, mem_tab);
    gather_kernel<<<R2 / 8, 256>>>(1, ngh_node2, ngh_eidx2, ngh_t2, d_perm2,
                                   cut_time, n_feat, mem_tab, e_feat, freq, phase);
    gemm_kernel<<<dim3(NOUT / 128, R2 / 128 + 1), 256, GEMM_SMEM>>>(1);
    qgemm_kernel<<<dim3(MDIM / 128, 256 / 128), 256, QGEMM_SMEM>>>(1, R2);
    attn_kernel<<<256 / NPB, 256, ATTN_SMEM>>>(1, R2, ngh_node2, d_perm2,
                                               Wm1, bm1, Wm2, bm2);

    final_kernel<<<BB, 128>>>(etype_l, Wmatch, bmatch, out);
}

// round 17
// speedup vs baseline: 1.8833x; 1.0068x over previous
#include <cuda_runtime.h>
#include <cuda_fp16.h>
#include <math.h>
#include <stdint.h>

#define KNB 40
#define DF 128
#define MDIM 384
#define HH 4
#define DHD 96
#define BB 128
#define R1 409600
#define R2 10240
#define KX2 384              // packed K: [nf | ef | tf]
#define NOUT 768             // g_Wt rows per (l,et): K outputs 0..383, V outputs 384..767
#define NV 384               // V-GEMM output width
#define NY 3072              // Y width: 2 et x 4 h x 384 m
#define NPB 8
#define KSTR 392             // padded halves per V row (784 B, 16-aligned)
#define SLOTH (KNB * KSTR)   // 15680 halves per V slot
#define QROWS (R2 + 256)     // 10496 query rows total

// ---------------- scratch (__device__ globals, no allocation) ----------------
__device__ __align__(16) __half g_X[(size_t)(R1 + 128) * KX2];
__device__ __align__(16) __half g_Wt[2 * 2 * NOUT * KX2];      // [l][et][n][k]
__device__ __align__(16) __half g_KV[(size_t)(R1 + 128) * NV]; // V projections
__device__ __align__(16) __half g_Xq[(size_t)QROWS * DF];      // query src features
__device__ __align__(16) __half g_Wqk[2 * NY * DF];            // folded Wq@Wk [l][c][mq]
__device__ __align__(16) __half g_Y[(size_t)QROWS * NY];       // folded query vectors
__device__ float g_yconst[2][NY];
__device__ float g_S[(size_t)QROWS * HH * KNB];                // masked, scaled scores
__device__ float g_qconst[2][384];
__device__ float g_WoM1[2][384 * 128];
__device__ float g_h1[R2 * DF];
__device__ float g_h2[256 * DF];
__device__ int g_cnt[4];
__device__ int g_meta[2];
__device__ int g_perm1[R1];
__device__ int g_perm2[R2];

// ---------------- helpers ----------------
__device__ __forceinline__ uint32_t smem_u32(const void* p) {
    return (uint32_t)__cvta_generic_to_shared((void*)p);
}
#define CP_ASYNC16(dst, src) \
    asm volatile("cp.async.cg.shared.global [%0], [%1], 16;" :: "r"(dst), "l"(src) : "memory")
#define CP_COMMIT() asm volatile("cp.async.commit_group;" ::: "memory")
#define CP_WAIT(n)  asm volatile("cp.async.wait_group %0;" :: "n"(n) : "memory")
#define LDSM_X4(d0, d1, d2, d3, addr) \
    asm volatile("ldmatrix.sync.aligned.m8n8.x4.shared.b16 {%0,%1,%2,%3}, [%4];" \
        : "=r"(d0), "=r"(d1), "=r"(d2), "=r"(d3) : "r"(addr))

__device__ __forceinline__ void mma16816(float* c, uint32_t a0, uint32_t a1,
                                         uint32_t a2, uint32_t a3,
                                         uint32_t b0, uint32_t b1) {
    asm volatile(
        "mma.sync.aligned.m16n8k16.row.col.f32.f16.f16.f32 "
        "{%0,%1,%2,%3}, {%4,%5,%6,%7}, {%8,%9}, {%0,%1,%2,%3};"
        : "+f"(c[0]), "+f"(c[1]), "+f"(c[2]), "+f"(c[3])
        : "r"(a0), "r"(a1), "r"(a2), "r"(a3), "r"(b0), "r"(b1));
}

// FMA-pipe cos: quadrant range reduction + polys on [-pi/4, pi/4].
__device__ __forceinline__ float fcospoly(float x) {
    float n = rintf(x * 0.6366197723675814f);
    float r = fmaf(n, -1.5707963705062866e0f, x);
    r = fmaf(n, 4.3711388286737929e-8f, r);
    int q = ((int)n) & 3;
    float r2 = r * r;
    float pc = fmaf(r2, fmaf(r2, fmaf(r2, -1.388888889e-3f, 4.166666667e-2f), -0.5f), 1.0f);
    float ps = r * fmaf(r2, fmaf(r2, fmaf(r2, -1.984126984e-4f, 8.333333333e-3f), -1.666666667e-1f), 1.0f);
    float v = (q & 1) ? ps : pc;
    return ((q + 1) & 2) ? -v : v;
}

// ---------------- partition: rank rows by etype ----------------
__global__ void partA_kernel(const int* __restrict__ et_arr, int* __restrict__ rank,
                             int cb) {
    int r = blockIdx.x * 256 + threadIdx.x;
    int et = (et_arr[r] != 0) ? 1 : 0;
    const unsigned m = 0xFFFFFFFFu;
    unsigned b1 = __ballot_sync(m, et == 1);
    unsigned b0 = ~b1;
    int lane = threadIdx.x & 31;
    unsigned lower = (1u << lane) - 1u;
    int base0 = 0, base1 = 0;
    int l0 = __ffs(b0) - 1, l1 = __ffs(b1) - 1;
    if (b0 && lane == l0) base0 = atomicAdd(&g_cnt[cb + 0], __popc(b0));
    if (b1 && lane == l1) base1 = atomicAdd(&g_cnt[cb + 1], __popc(b1));
    if (b0) base0 = __shfl_sync(m, base0, l0);
    if (b1) base1 = __shfl_sync(m, base1, l1);
    rank[r] = et ? (base1 + __popc(b1 & lower)) : (base0 + __popc(b0 & lower));
}
__global__ void partB_kernel(const int* __restrict__ et_arr, int* __restrict__ perm,
                             int cb, int layer) {
    int r = blockIdx.x * 256 + threadIdx.x;
    int c0 = g_cnt[cb + 0];
    int tiles0 = (c0 + 127) >> 7;
    int et = (et_arr[r] != 0) ? 1 : 0;
    int rk = perm[r];
    perm[r] = et ? (tiles0 * 128 + rk) : rk;
    if (r == 0) g_meta[layer] = tiles0;
}

// ------------- precompute 1: fused K|V weights + qconst + WoM1 ---------------
__global__ void pre_all(const float* __restrict__ Wrel,
                        const float* __restrict__ Wk,
                        const float* __restrict__ Wv,
                        const float* __restrict__ Wq,
                        const float* __restrict__ Wo,
                        const float* __restrict__ Wm1,
                        const float* __restrict__ phase) {
    int b = blockIdx.x;
    int tid = threadIdx.x;             // 384
    if (b < 3072) {
        if (tid < 128) {
            int l = b / (2 * NOUT);
            int rem = b % (2 * NOUT);
            int et = rem / NOUT;
            int n = rem % NOUT;
            const float* Ws = ((n < MDIM) ? Wk : Wv) + (size_t)l * MDIM * MDIM;
            int nc = (n < MDIM) ? n : n - MDIM;
            const float* wr = Wrel + ((size_t)(l * 2 + et) * DF + tid) * DF;
            float v = 0.f;
            for (int j = 0; j < DF; j++)
                v = fmaf(wr[j], Ws[(size_t)j * MDIM + nc], v);
            size_t base = ((size_t)((l * 2 + et) * NOUT) + n) * KX2;
            g_Wt[base + tid]        = __float2half_rn(v);
            g_Wt[base + 128 + tid]  = __float2half_rn(Ws[(size_t)(DF + tid) * MDIM + nc]);
            g_Wt[base + 256 + tid]  = __float2half_rn(Ws[(size_t)(256 + tid) * MDIM + nc]);
        }
    } else {
        int bid = b - 3072;            // 770 = 2*(384+1)
        int l = bid / 385;
        int r = bid % 385;
        if (r == 384) {
            float acc = 0.f;
            for (int j = 0; j < 128; j++)
                acc = fmaf(cosf(phase[j]), Wq[(size_t)l * MDIM * MDIM + (256 + j) * MDIM + tid], acc);
            g_qconst[l][tid] = acc;
        } else if (tid < 128) {
            float acc = 0.f;
            for (int j = 0; j < MDIM; j++)
                acc = fmaf(Wo[(size_t)l * MDIM * MDIM + r * MDIM + j],
                           Wm1[(size_t)(l * 512 + j) * 128 + tid], acc);
            g_WoM1[l][r * 128 + tid] = acc;
        }
    }
}

// ------------- precompute 2: folded Wqk = Wq @ Wk_fused (needs pre_all) ------
// c = et*1536 + h*384 + m. Wqk[mq,c] = sum_d Wq[mq, h*96+d] * Wk_f[et][h*96+d, m]
__global__ void pre_all2(const float* __restrict__ Wq) {
    int b = blockIdx.x;                 // 2*NY
    int l = b / NY, c = b % NY;
    int et = c / 1536;
    int hc = c % 1536;
    int h = hc / 384, m = hc % 384;
    int mq = threadIdx.x;               // 128
    const __half* wkrow = g_Wt + ((size_t)((l * 2 + et) * NOUT) + h * 96) * KX2 + m;
    const float* wq = Wq + (size_t)l * MDIM * MDIM + (size_t)mq * MDIM + h * 96;
    float acc = 0.f;
    for (int d = 0; d < 96; d++)
        acc = fmaf(wq[d], __half2float(wkrow[(size_t)d * KX2]), acc);
    g_Wqk[((size_t)l * NY + c) * DF + mq] = __float2half_rn(acc);
    if (mq == 0) {
        float yc = 0.f;
        for (int d = 0; d < 96; d++)
            yc = fmaf(g_qconst[l][h * 96 + d], __half2float(wkrow[(size_t)d * KX2]), yc);
        g_yconst[l][c] = yc;
    }
}

// ---------------- qgather: query src features (fp16) ----------------
__global__ void qgather_kernel(int layer, const int* __restrict__ srcA,
                               const int* __restrict__ srcB,
                               const float* __restrict__ n_feat,
                               const float* __restrict__ mem_tab) {
    int n = blockIdx.x * 8 + (threadIdx.x >> 5);
    int u = threadIdx.x & 31;
    int sid = (layer == 0) ? srcA[n] : ((n < BB) ? srcA[n] : srcB[n - BB]);
    int j = 4 * u;
    float4 a = *(const float4*)(n_feat + (size_t)sid * DF + j);
    float4 bb = *(const float4*)(mem_tab + (size_t)sid * DF + j);
    int qrow = ((layer == 0) ? 0 : R2) + n;
    __half2* dst = (__half2*)(g_Xq + (size_t)qrow * DF);
    dst[2 * u]     = __floats2half2_rn(a.x + bb.x, a.y + bb.y);
    dst[2 * u + 1] = __floats2half2_rn(a.z + bb.z, a.w + bb.w);
}

// ---------------- gather: packed X rows (fp16, 4 cols/thread) ----------------
__global__ void gather_kernel(int layer, const int* __restrict__ nghNode,
                              const int* __restrict__ nghEidx,
                              const float* __restrict__ nghT,
                              const int* __restrict__ perm,
                              const float* __restrict__ parentT,
                              const float* __restrict__ n_feat,
                              const float* __restrict__ mem_tab,
                              const float* __restrict__ e_feat,
                              const float* __restrict__ freq,
                              const float* __restrict__ phase) {
    int r = blockIdx.x * 8 + (threadIdx.x >> 5);
    int u = threadIdx.x & 31;
    int node = nghNode[r];
    int eidx = nghEidx[r];
    int pos = perm[r];
    int p = r / KNB;
    float tq = (layer == 0) ? parentT[p] : parentT[p & (BB - 1)];
    float dt = tq - nghT[r];
    int j = 4 * u;
    float4 nf4;
    if (layer == 0) {
        float4 a = *(const float4*)(n_feat + (size_t)node * DF + j);
        float4 b = *(const float4*)(mem_tab + (size_t)node * DF + j);
        nf4 = make_float4(a.x + b.x, a.y + b.y, a.z + b.z, a.w + b.w);
    } else {
        nf4 = *(const float4*)(g_h1 + (size_t)r * DF + j);
    }
    float4 ef4 = *(const float4*)(e_feat + (size_t)eidx * DF + j);
    float4 fr4 = *(const float4*)(freq + j);
    float4 ph4 = *(const float4*)(phase + j);
    float t0 = fcospoly(fmaf(dt, fr4.x, ph4.x));
    float t1 = fcospoly(fmaf(dt, fr4.y, ph4.y));
    float t2 = fcospoly(fmaf(dt, fr4.z, ph4.z));
    float t3 = fcospoly(fmaf(dt, fr4.w, ph4.w));
    __half2* dst = (__half2*)(g_X + (size_t)pos * KX2);
    dst[2 * u]           = __floats2half2_rn(nf4.x, nf4.y);
    dst[2 * u + 1]       = __floats2half2_rn(nf4.z, nf4.w);
    dst[64 + 2 * u]      = __floats2half2_rn(ef4.x, ef4.y);
    dst[64 + 2 * u + 1]  = __floats2half2_rn(ef4.z, ef4.w);
    dst[128 + 2 * u]     = __floats2half2_rn(t0, t1);
    dst[128 + 2 * u + 1] = __floats2half2_rn(t2, t3);
}

// ---------------- HMMA V-GEMM: V = X @ Wv_fused[et]' ----------------
#define STR 72                         // padded smem stride in halves (144B rows)
#define ABYTES (128 * STR * 2)         // 18432
#define BUFB   (2 * ABYTES)            // 36864 per stage (A + B)
#define NCHK   (KX2 / 64)              // 6
__global__ __launch_bounds__(256, 2)
void gemm_kernel(int layer) {
    extern __shared__ char smem[];
    const uint32_t smem_base = smem_u32(smem);
    const int tid = threadIdx.x;
    const int wid = tid >> 5;
    const int lane = tid & 31;
    const int n0 = blockIdx.x * 128;
    const int m0 = blockIdx.y * 128;
    const int mbase = (wid >> 1) * 32;
    const int nbase = (wid & 1) * 64;

    const int lrow = lane & 15;
    const int akh  = (lane >> 4) * 8;
    const int brow = (lane & 7) + ((lane >> 4) * 8);
    const int bkh  = ((lane >> 3) & 1) * 8;

    const int tiles0 = g_meta[layer];
    const int et = ((int)blockIdx.y >= tiles0) ? 1 : 0;
    // V block: rows 384..767 of the fused weights
    const __half* gW = g_Wt + ((size_t)((layer * 2 + et) * NOUT) + MDIM) * KX2;

    float acc[2][8][4];
#pragma unroll
    for (int mt = 0; mt < 2; mt++)
#pragma unroll
        for (int nt = 0; nt < 8; nt++)
#pragma unroll
            for (int q = 0; q < 4; q++) acc[mt][nt][q] = 0.f;

    auto stage = [&](int c) {
        const int kb = c * 64;
        const uint32_t sbase = smem_base + (c % 3) * BUFB;
#pragma unroll
        for (int it = 0; it < 8; it++) {
            int i = tid + it * 256;
            int isB = i >> 10;
            int j = i & 1023;
            int row = j >> 3, seg = j & 7;
            uint32_t dst = sbase + isB * ABYTES + (uint32_t)(row * STR + seg * 8) * 2;
            const __half* src = isB ? (gW + (size_t)(n0 + row) * KX2 + kb + seg * 8)
                                    : (g_X + (size_t)(m0 + row) * KX2 + kb + seg * 8);
            CP_ASYNC16(dst, src);
        }
        CP_COMMIT();
    };

    stage(0);
    stage(1);
    for (int c = 0; c < NCHK; c++) {
        if (c < NCHK - 1) CP_WAIT(1); else CP_WAIT(0);
        __syncthreads();
        const uint32_t sA = smem_base + (c % 3) * BUFB;
        const uint32_t sB = sA + ABYTES;
#pragma unroll
        for (int ks = 0; ks < 4; ks++) {
            const int k16 = ks * 16;
            uint32_t bf[8][2];
#pragma unroll
            for (int nt2 = 0; nt2 < 4; nt2++) {
                uint32_t d0, d1, d2, d3;
                uint32_t addr = sB + (uint32_t)((nbase + nt2 * 16 + brow) * STR + k16 + bkh) * 2;
                LDSM_X4(d0, d1, d2, d3, addr);
                bf[nt2 * 2][0] = d0; bf[nt2 * 2][1] = d1;
                bf[nt2 * 2 + 1][0] = d2; bf[nt2 * 2 + 1][1] = d3;
            }
#pragma unroll
            for (int mt = 0; mt < 2; mt++) {
                uint32_t a0, a1, a2, a3;
                uint32_t addr = sA + (uint32_t)((mbase + mt * 16 + lrow) * STR + k16 + akh) * 2;
                LDSM_X4(a0, a1, a2, a3, addr);
#pragma unroll
                for (int nt = 0; nt < 8; nt++)
                    mma16816(acc[mt][nt], a0, a1, a2, a3, bf[nt][0], bf[nt][1]);
            }
        }
        if (c + 2 < NCHK) stage(c + 2);
    }

#pragma unroll
    for (int mt = 0; mt < 2; mt++) {
#pragma unroll
        for (int nt = 0; nt < 8; nt++) {
            int r = m0 + mbase + mt * 16 + (lane >> 2);
            int ccol = n0 + nbase + nt * 8 + (lane & 3) * 2;
            *(__half2*)(g_KV + (size_t)r * NV + ccol) =
                __floats2half2_rn(acc[mt][nt][0], acc[mt][nt][1]);
            *(__half2*)(g_KV + (size_t)(r + 8) * NV + ccol) =
                __floats2half2_rn(acc[mt][nt][2], acc[mt][nt][3]);
        }
    }
}

// ---------------- HMMA Y-GEMM: Y = Xq @ Wqk' + yconst (fp16 out) -------------
__global__ __launch_bounds__(256, 2)
void ygemm_kernel(int layer, int qbase) {
    extern __shared__ char smem[];
    const uint32_t smem_base = smem_u32(smem);
    const int tid = threadIdx.x;
    const int wid = tid >> 5;
    const int lane = tid & 31;
    const int n0 = blockIdx.x * 128;
    const int m0 = blockIdx.y * 128;
    const int mbase = (wid >> 1) * 32;
    const int nbase = (wid & 1) * 64;

    const int lrow = lane & 15;
    const int akh  = (lane >> 4) * 8;
    const int brow = (lane & 7) + ((lane >> 4) * 8);
    const int bkh  = ((lane >> 3) & 1) * 8;

    const __half* gW = g_Wqk + (size_t)layer * NY * DF;

    float acc[2][8][4];
#pragma unroll
    for (int mt = 0; mt < 2; mt++)
#pragma unroll
        for (int nt = 0; nt < 8; nt++)
#pragma unroll
            for (int q = 0; q < 4; q++) acc[mt][nt][q] = 0.f;

    auto stage = [&](int c) {
        const int kb = c * 64;
        const uint32_t sbase = smem_base + c * BUFB;
#pragma unroll
        for (int it = 0; it < 8; it++) {
            int i = tid + it * 256;
            int isB = i >> 10;
            int j = i & 1023;
            int row = j >> 3, seg = j & 7;
            uint32_t dst = sbase + isB * ABYTES + (uint32_t)(row * STR + seg * 8) * 2;
            const __half* src = isB ? (gW + (size_t)(n0 + row) * DF + kb + seg * 8)
                                    : (g_Xq + (size_t)(qbase + m0 + row) * DF + kb + seg * 8);
            CP_ASYNC16(dst, src);
        }
        CP_COMMIT();
    };

    stage(0);
    stage(1);
    for (int c = 0; c < 2; c++) {
        if (c == 0) CP_WAIT(1); else CP_WAIT(0);
        __syncthreads();
        const uint32_t sA = smem_base + c * BUFB;
        const uint32_t sB = sA + ABYTES;
#pragma unroll
        for (int ks = 0; ks < 4; ks++) {
            const int k16 = ks * 16;
            uint32_t bf[8][2];
#pragma unroll
            for (int nt2 = 0; nt2 < 4; nt2++) {
                uint32_t d0, d1, d2, d3;
                uint32_t addr = sB + (uint32_t)((nbase + nt2 * 16 + brow) * STR + k16 + bkh) * 2;
                LDSM_X4(d0, d1, d2, d3, addr);
                bf[nt2 * 2][0] = d0; bf[nt2 * 2][1] = d1;
                bf[nt2 * 2 + 1][0] = d2; bf[nt2 * 2 + 1][1] = d3;
            }
#pragma unroll
            for (int mt = 0; mt < 2; mt++) {
                uint32_t a0, a1, a2, a3;
                uint32_t addr = sA + (uint32_t)((mbase + mt * 16 + lrow) * STR + k16 + akh) * 2;
                LDSM_X4(a0, a1, a2, a3, addr);
#pragma unroll
                for (int nt = 0; nt < 8; nt++)
                    mma16816(acc[mt][nt], a0, a1, a2, a3, bf[nt][0], bf[nt][1]);
            }
        }
        __syncthreads();
    }

#pragma unroll
    for (int mt = 0; mt < 2; mt++) {
#pragma unroll
        for (int nt = 0; nt < 8; nt++) {
            int r = m0 + mbase + mt * 16 + (lane >> 2);
            int ccol = n0 + nbase + nt * 8 + (lane & 3) * 2;
            float y0 = acc[mt][nt][0] + g_yconst[layer][ccol];
            float y1 = acc[mt][nt][1] + g_yconst[layer][ccol + 1];
            float y2 = acc[mt][nt][2] + g_yconst[layer][ccol];
            float y3 = acc[mt][nt][3] + g_yconst[layer][ccol + 1];
            *(__half2*)(g_Y + (size_t)(qbase + r) * NY + ccol) = __floats2half2_rn(y0, y1);
            *(__half2*)(g_Y + (size_t)(qbase + r + 8) * NY + ccol) = __floats2half2_rn(y2, y3);
        }
    }
}

// ---------------- scores: s[r,h] = scale * X[perm[r]] . Y[n,et,h] ------------
// one warp per neighbor row; masked rows get -1e9 directly.
__global__ void scores_kernel(int layer, int qbase, const int* __restrict__ nghNode,
                              const int* __restrict__ nghEt,
                              const int* __restrict__ perm) {
    int r = blockIdx.x * 8 + (threadIdx.x >> 5);
    int lane = threadIdx.x & 31;
    int n = r / KNB, kpos = r % KNB;
    int et = (nghEt[r] != 0) ? 1 : 0;
    int pos = perm[r];
    const __half2* x2 = (const __half2*)(g_X + (size_t)pos * KX2);
    const __half2* y2 = (const __half2*)(g_Y + (size_t)(qbase + n) * NY + et * 1536);
    float2 xv[6];
#pragma unroll
    for (int t = 0; t < 6; t++) xv[t] = __half22float2(x2[lane + 32 * t]);
    float acc[4];
#pragma unroll
    for (int h = 0; h < 4; h++) {
        const __half2* yh = y2 + h * 192;
        float s = 0.f;
#pragma unroll
        for (int t = 0; t < 6; t++) {
            float2 yv = __half22float2(yh[lane + 32 * t]);
            s = fmaf(xv[t].x, yv.x, s);
            s = fmaf(xv[t].y, yv.y, s);
        }
        acc[h] = s;
    }
#pragma unroll
    for (int o = 16; o > 0; o >>= 1) {
#pragma unroll
        for (int h = 0; h < 4; h++)
            acc[h] += __shfl_xor_sync(0xFFFFFFFF, acc[h], o);
    }
    if (lane == 0) {
        bool msk = (nghNode[r] == 0);
        float* dst = g_S + (size_t)(qbase + n) * (HH * KNB) + kpos;
#pragma unroll
        for (int h = 0; h < 4; h++)
            dst[h * KNB] = msk ? -1000000000.0f : acc[h] * 0.10206207261596577f;
    }
}

// ---------------- attention + MLP: 8 nodes/CTA, V-only double buffer ---------
__global__ __launch_bounds__(256, 2)
void attn_kernel(int layer, int qbase, const int* __restrict__ perm,
                 const float* __restrict__ Wm1, const float* __restrict__ bm1,
                 const float* __restrict__ Wm2, const float* __restrict__ bm2) {
    extern __shared__ float sm[];
    __half* sSlot = (__half*)sm;             // 2*15680 halves = 15680 floats
    __half* sSRCh = (__half*)(sm + 15680);   // 8*128 halves = 512 floats
    float*  sS    = sm + 16192;              // 160
    float*  sO    = sm + 16352;              // 3072 -> ends 19424 (77696 B)
    float*  sA1   = sm;                      // overlay on slots after node loop
    const int tid = threadIdx.x;
    const int nb = blockIdx.x;
    const uint32_t smem_base = smem_u32(sm);

    {   // src features (fp16, from g_Xq)
        const uint4* ssrc = (const uint4*)(g_Xq + (size_t)(qbase + nb * NPB) * DF);
        for (int v = tid; v < NPB * DF / 8; v += 256)
            ((uint4*)sSRCh)[v] = ssrc[v];
    }

    auto stageV = [&](int i, int buf) {
        const int nKNB = (nb * NPB + i) * KNB;
        const uint32_t dbase = smem_base + (uint32_t)buf * (SLOTH * 2);
        for (int v = tid; v < KNB * 48; v += 256) {
            int row = v / 48, seg = v % 48;
            const __half* src = g_KV + (size_t)perm[nKNB + row] * NV + seg * 8;
            CP_ASYNC16(dbase + (uint32_t)(row * KSTR + seg * 8) * 2, src);
        }
        CP_COMMIT();
    };
    stageV(0, 0);

    for (int i = 0; i < NPB; i++) {
        if (i < NPB - 1) stageV(i + 1, (i + 1) & 1);
        if (tid < HH * KNB)
            sS[tid] = g_S[(size_t)(qbase + nb * NPB + i) * (HH * KNB) + tid];
        __syncthreads();
        // warp-parallel softmax (scores pre-masked, pre-scaled)
        if (tid < 128) {
            int h = tid >> 5, lane = tid & 31;
            float v0 = sS[h * KNB + lane];
            float v1 = (lane < 8) ? sS[h * KNB + 32 + lane] : -INFINITY;
            float mx = fmaxf(v0, v1);
#pragma unroll
            for (int o = 16; o > 0; o >>= 1)
                mx = fmaxf(mx, __shfl_xor_sync(0xFFFFFFFF, mx, o));
            float e0 = expf(v0 - mx);
            float e1 = (lane < 8) ? expf(v1 - mx) : 0.f;
            float sum = e0 + e1;
#pragma unroll
            for (int o = 16; o > 0; o >>= 1)
                sum += __shfl_xor_sync(0xFFFFFFFF, sum, o);
            float inv = 1.f / sum;
            sS[h * KNB + lane] = e0 * inv;
            if (lane < 8) sS[h * KNB + 32 + lane] = e1 * inv;
        }
        if (i < NPB - 1) CP_WAIT(1); else CP_WAIT(0);   // V(i) ready
        __syncthreads();
        const __half* vb = sSlot + (i & 1) * SLOTH;
        for (int cc = tid; cc < MDIM; cc += 256) {
            int h = cc / DHD;
            const float* a = sS + h * KNB;
            float o = 0.f;
            for (int k = 0; k < KNB; k++)
                o = fmaf(a[k], __half2float(vb[k * KSTR + cc]), o);
            sO[i * MDIM + cc] = o;
        }
        __syncthreads();                 // V(i)+sS consumed before next overwrite
    }

    // MLP layer 1 (Wo folded into WoM1): 2 thread-halves x 4 nodes each
    {
        const int half = tid >> 7, col = tid & 127;
        float a[4];
#pragma unroll
        for (int i = 0; i < 4; i++) a[i] = bm1[layer * DF + col];
        const float* w1 = &g_WoM1[layer][col];
        for (int m = 0; m < MDIM; m++) {
            float w = w1[m * DF];
#pragma unroll
            for (int i = 0; i < 4; i++)
                a[i] = fmaf(sO[(half * 4 + i) * MDIM + m], w, a[i]);
        }
        const float* w1b = Wm1 + (size_t)(layer * 512 + MDIM) * DF + col;
        for (int m = 0; m < DF; m++) {
            float w = w1b[m * DF];
#pragma unroll
            for (int i = 0; i < 4; i++)
                a[i] = fmaf(__half2float(sSRCh[(half * 4 + i) * DF + m]), w, a[i]);
        }
#pragma unroll
        for (int i = 0; i < 4; i++) sA1[(half * 4 + i) * DF + col] = fmaxf(a[i], 0.f);
    }
    __syncthreads();
    {
        const int half = tid >> 7, col = tid & 127;
        float a[4];
#pragma unroll
        for (int i = 0; i < 4; i++) a[i] = bm2[layer * DF + col];
        const float* w2 = Wm2 + (size_t)layer * DF * DF + col;
        for (int d = 0; d < DF; d++) {
            float w = w2[d * DF];
#pragma unroll
            for (int i = 0; i < 4; i++)
                a[i] = fmaf(sA1[(half * 4 + i) * DF + d], w, a[i]);
        }
        float* hout = (layer == 0) ? g_h1 : g_h2;
#pragma unroll
        for (int i = 0; i < 4; i++)
            hout[(size_t)(nb * NPB + half * 4 + i) * DF + col] = a[i];
    }
}

// ---------------- final bilinear score + sigmoid (+ counter reset) ----------
__global__ void final_kernel(const int* __restrict__ etype_l,
                             const float* __restrict__ Wmatch,
                             const float* __restrict__ bmatch,
                             float* __restrict__ out) {
    __shared__ float ste[128];
    __shared__ float red[128];
    int b = blockIdx.x, d = threadIdx.x;
    if (b == 0 && d < 4) g_cnt[d] = 0;
    int et = etype_l[b];
    ste[d] = g_h2[(BB + b) * DF + d];
    __syncthreads();
    float se = g_h2[b * DF + d];
    const float* wm = Wmatch + (size_t)(et * DF + d) * DF;
    float v = 0.f;
    for (int e = 0; e < DF; e++) v = fmaf(wm[e], ste[e], v);
    red[d] = se * v;
    __syncthreads();
    for (int s = 64; s > 0; s >>= 1) {
        if (d < s) red[d] += red[d + s];
        __syncthreads();
    }
    if (d == 0) {
        float score = red[0] + bmatch[et];
        out[b] = 1.f / (1.f + expf(-score));
    }
}

extern "C" void kernel_launch(void* const* d_in, const int* in_sizes, int n_in,
                              void* d_out, int out_size) {
    const int*   src_idx   = (const int*)d_in[0];
    const int*   tgt_idx   = (const int*)d_in[1];
    const float* cut_time  = (const float*)d_in[2];
    const int*   etype_l   = (const int*)d_in[5];
    const int*   ngh_node2 = (const int*)d_in[6];
    const int*   ngh_eidx2 = (const int*)d_in[7];
    const float* ngh_t2    = (const float*)d_in[8];
    const int*   ngh_et2   = (const int*)d_in[9];
    const int*   ngh_node1 = (const int*)d_in[11];
    const int*   ngh_eidx1 = (const int*)d_in[12];
    const float* ngh_t1    = (const float*)d_in[13];
    const int*   ngh_et1   = (const int*)d_in[14];
    const float* n_feat    = (const float*)d_in[16];
    const float* e_feat    = (const float*)d_in[17];
    const float* mem_tab   = (const float*)d_in[18];
    const float* freq      = (const float*)d_in[19];
    const float* phase     = (const float*)d_in[20];
    const float* Wq        = (const float*)d_in[21];
    const float* Wk        = (const float*)d_in[22];
    const float* Wv        = (const float*)d_in[23];
    const float* Wo        = (const float*)d_in[24];
    const float* Wm1       = (const float*)d_in[25];
    const float* bm1       = (const float*)d_in[26];
    const float* Wm2       = (const float*)d_in[27];
    const float* bm2       = (const float*)d_in[28];
    const float* Wrel      = (const float*)d_in[29];
    const float* Wmatch    = (const float*)d_in[30];
    const float* bmatch    = (const float*)d_in[31];
    float* out = (float*)d_out;

    int* d_perm1; cudaGetSymbolAddress((void**)&d_perm1, g_perm1);
    int* d_perm2; cudaGetSymbolAddress((void**)&d_perm2, g_perm2);

    const int GEMM_SMEM = 3 * BUFB;              // 110592 B
    const int YGEMM_SMEM = 2 * BUFB;             // 73728 B
    const int ATTN_SMEM = 19424 * 4;             // 77696 B (2 CTAs/SM)
    cudaFuncSetAttribute(gemm_kernel, cudaFuncAttributeMaxDynamicSharedMemorySize, GEMM_SMEM);
    cudaFuncSetAttribute(ygemm_kernel, cudaFuncAttributeMaxDynamicSharedMemorySize, YGEMM_SMEM);
    cudaFuncSetAttribute(attn_kernel, cudaFuncAttributeMaxDynamicSharedMemorySize, ATTN_SMEM);

    // ---- layer 0 ----
    partA_kernel<<<R1 / 256, 256>>>(ngh_et1, d_perm1, 0);
    partB_kernel<<<R1 / 256, 256>>>(ngh_et1, d_perm1, 0, 0);
    pre_all<<<3842, 384>>>(Wrel, Wk, Wv, Wq, Wo, Wm1, phase);
    pre_all2<<<2 * NY, 128>>>(Wq);
    qgather_kernel<<<R2 / 8, 256>>>(0, ngh_node2, (const int*)0, n_feat, mem_tab);
    gather_kernel<<<R1 / 8, 256>>>(0, ngh_node1, ngh_eidx1, ngh_t1, d_perm1,
                                   ngh_t2, n_feat, mem_tab, e_feat, freq, phase);
    gemm_kernel<<<dim3(NV / 128, R1 / 128 + 1), 256, GEMM_SMEM>>>(0);
    ygemm_kernel<<<dim3(NY / 128, R2 / 128), 256, YGEMM_SMEM>>>(0, 0);
    scores_kernel<<<R1 / 8, 256>>>(0, 0, ngh_node1, ngh_et1, d_perm1);
    attn_kernel<<<R2 / NPB, 256, ATTN_SMEM>>>(0, 0, d_perm1, Wm1, bm1, Wm2, bm2);

    // ---- layer 1 ----
    partA_kernel<<<R2 / 256, 256>>>(ngh_et2, d_perm2, 2);
    partB_kernel<<<R2 / 256, 256>>>(ngh_et2, d_perm2, 2, 1);
    qgather_kernel<<<256 / 8, 256>>>(1, src_idx, tgt_idx, n_feat, mem_tab);
    gather_kernel<<<R2 / 8, 256>>>(1, ngh_node2, ngh_eidx2, ngh_t2, d_perm2,
                                   cut_time, n_feat, mem_tab, e_feat, freq, phase);
    gemm_kernel<<<dim3(NV / 128, R2 / 128 + 1), 256, GEMM_SMEM>>>(1);
    ygemm_kernel<<<dim3(NY / 128, 256 / 128), 256, YGEMM_SMEM>>>(1, R2);
    scores_kernel<<<R2 / 8, 256>>>(1, R2, ngh_node2, ngh_et2, d_perm2);
    attn_kernel<<<256 / NPB, 256, ATTN_SMEM>>>(1, R2, d_perm2, Wm1, bm1, Wm2, bm2);

    final_kernel<<<BB, 128>>>(etype_l, Wmatch, bmatch, out);
}